// round 1
// baseline (speedup 1.0000x reference)
#include <cuda_runtime.h>
#include <math.h>

// Problem constants (shape is fixed by the dataset)
#define NMAX 500000
#define NGROUPS 8

// Scratch (device globals: no allocation allowed in kernel_launch)
__device__ float g_h1[(size_t)NMAX * 64];  // conv1 output (post-SiLU)
__device__ float g_stats[16];              // per-group {sum, sumsq}
__device__ float g_scale[64];              // fused GN affine scale
__device__ float g_bias[64];               // fused GN affine bias

// ---------------------------------------------------------------------------
// GroupNorm statistics
// ---------------------------------------------------------------------------
__global__ void zero_stats_kernel() {
    if (threadIdx.x < 16) g_stats[threadIdx.x] = 0.f;
}

template <int C>
__global__ void gn_reduce_kernel(const float* __restrict__ x, int n) {
    constexpr int Q = C / 4;        // float4 per row
    constexpr int CPG = C / NGROUPS;
    int tid = blockIdx.x * blockDim.x + threadIdx.x;
    int total = gridDim.x * blockDim.x;        // multiple of Q by construction
    int q = tid & (Q - 1);                     // fixed per thread
    int g = (q * 4) / CPG;                     // one group per float4
    float s = 0.f, ss = 0.f;
    long nQ = (long)n * Q;
    const float4* xp = (const float4*)x;
    for (long e = tid; e < nQ; e += total) {
        float4 v = xp[e];
        s += (v.x + v.y) + (v.z + v.w);
        ss += v.x * v.x + v.y * v.y + v.z * v.z + v.w * v.w;
    }
    __shared__ float sh[16];
    if (threadIdx.x < 16) sh[threadIdx.x] = 0.f;
    __syncthreads();
    atomicAdd(&sh[2 * g], s);
    atomicAdd(&sh[2 * g + 1], ss);
    __syncthreads();
    if (threadIdx.x < 16) atomicAdd(&g_stats[threadIdx.x], sh[threadIdx.x]);
}

template <int C>
__global__ void gn_finalize_kernel(const float* __restrict__ gamma,
                                   const float* __restrict__ beta, int n) {
    int c = threadIdx.x;
    if (c < C) {
        int g = c / (C / NGROUPS);
        float cnt = (float)n * (C / NGROUPS);
        float mean = g_stats[2 * g] / cnt;
        float var = g_stats[2 * g + 1] / cnt - mean * mean;
        float sc = gamma[c] * rsqrtf(var + 1e-5f);
        g_scale[c] = sc;
        g_bias[c] = beta[c] - mean * sc;
    }
}

// ---------------------------------------------------------------------------
// Gather-conv: out[v, 0:64] (+)= [SiLU]( sum_k affine(x[nbr[v,k]]) @ W[k] ) [+ obias]
// Tile: 256 voxels x 64 outputs per block, 256 threads, 8x8 register tile.
// ---------------------------------------------------------------------------
template <int CIN, int KT, bool GATHER, bool AFFINE, bool SILU_EN, bool ACCUM, bool BIAS>
__global__ void __launch_bounds__(256, 2)
conv_kernel(const float* __restrict__ xin,
            const int* __restrict__ nbr,
            const float* __restrict__ W,       // [KT][CIN][64]
            const float* __restrict__ obias,   // [64] or null
            float* __restrict__ out, int n) {
    constexpr int TM = 256;
    constexpr int NCH = CIN / 32;
    __shared__ float As[32][TM + 4];   // channel-major gathered inputs (padded)
    __shared__ float Bs[32][64];       // weight chunk
    __shared__ int Nk[TM];

    const int tid = threadIdx.x;
    const int v0 = blockIdx.x * TM;
    const int vv = tid >> 3;           // voxel group 0..31 (8 voxels each)
    const int ov = tid & 7;            // output group: o = ov*4+j and 32+ov*4+j
    const int c4 = (tid & 7) << 2;     // gather channel base within chunk

    float acc[8][8];
#pragma unroll
    for (int i = 0; i < 8; ++i)
#pragma unroll
        for (int j = 0; j < 8; ++j) acc[i][j] = 0.f;

    for (int k = 0; k < KT; ++k) {
        {
            int v = v0 + tid;
            int vc = v < n ? v : (n - 1);
            if constexpr (GATHER)
                Nk[tid] = nbr[(long)vc * KT + k];
            else
                Nk[tid] = vc;
        }
        __syncthreads();
#pragma unroll
        for (int ch = 0; ch < NCH; ++ch) {
            const int c0 = ch * 32;
            // stage W[k][c0:c0+32][0:64] into Bs (contiguous copy)
            {
                const float4* Wp = (const float4*)(W + ((long)k * CIN + c0) * 64);
                float4* Bp = (float4*)(&Bs[0][0]);
                Bp[tid] = Wp[tid];
                Bp[tid + 256] = Wp[tid + 256];
            }
            // affine params for this thread's 4 channels
            float s0 = 1.f, s1 = 1.f, s2 = 1.f, s3 = 1.f;
            float b0 = 0.f, b1 = 0.f, b2 = 0.f, b3 = 0.f;
            if constexpr (AFFINE) {
                s0 = g_scale[c0 + c4 + 0]; s1 = g_scale[c0 + c4 + 1];
                s2 = g_scale[c0 + c4 + 2]; s3 = g_scale[c0 + c4 + 3];
                b0 = g_bias[c0 + c4 + 0];  b1 = g_bias[c0 + c4 + 1];
                b2 = g_bias[c0 + c4 + 2];  b3 = g_bias[c0 + c4 + 3];
            }
            // gather 256 rows (transposed into As)
#pragma unroll
            for (int it = 0; it < 8; ++it) {
                int v = it * 32 + (tid >> 3);
                int j = Nk[v];
                float4 xv = *(const float4*)(xin + (long)j * CIN + c0 + c4);
                if constexpr (AFFINE) {
                    xv.x = fmaf(xv.x, s0, b0);
                    xv.y = fmaf(xv.y, s1, b1);
                    xv.z = fmaf(xv.z, s2, b2);
                    xv.w = fmaf(xv.w, s3, b3);
                }
                As[c4 + 0][v] = xv.x;
                As[c4 + 1][v] = xv.y;
                As[c4 + 2][v] = xv.z;
                As[c4 + 3][v] = xv.w;
            }
            __syncthreads();
            // 8x8 register-tile GEMM over the 32-channel chunk
#pragma unroll
            for (int c = 0; c < 32; ++c) {
                float a[8], b[8];
                *(float4*)&a[0] = *(const float4*)&As[c][vv * 8];
                *(float4*)&a[4] = *(const float4*)&As[c][vv * 8 + 4];
                *(float4*)&b[0] = *(const float4*)&Bs[c][ov * 4];
                *(float4*)&b[4] = *(const float4*)&Bs[c][32 + ov * 4];
#pragma unroll
                for (int i = 0; i < 8; ++i)
#pragma unroll
                    for (int j = 0; j < 8; ++j)
                        acc[i][j] = fmaf(a[i], b[j], acc[i][j]);
            }
            __syncthreads();
        }
    }

    // epilogue
    float ob[8];
#pragma unroll
    for (int j = 0; j < 8; ++j) ob[j] = 0.f;
    if constexpr (BIAS) {
#pragma unroll
        for (int j = 0; j < 4; ++j) {
            ob[j] = obias[ov * 4 + j];
            ob[4 + j] = obias[32 + ov * 4 + j];
        }
    }
#pragma unroll
    for (int i = 0; i < 8; ++i) {
        int v = v0 + vv * 8 + i;
        if (v < n) {
            float r[8];
#pragma unroll
            for (int j = 0; j < 8; ++j) {
                float t = acc[i][j];
                if constexpr (SILU_EN) t = t / (1.f + __expf(-t));
                r[j] = t + ob[j];
            }
            float* po = out + (long)v * 64 + ov * 4;
            if constexpr (ACCUM) {
                float4 e0 = *(const float4*)po;
                float4 e1 = *(const float4*)(po + 32);
                r[0] += e0.x; r[1] += e0.y; r[2] += e0.z; r[3] += e0.w;
                r[4] += e1.x; r[5] += e1.y; r[6] += e1.z; r[7] += e1.w;
            }
            *(float4*)po = make_float4(r[0], r[1], r[2], r[3]);
            *(float4*)(po + 32) = make_float4(r[4], r[5], r[6], r[7]);
        }
    }
}

// feat_depth (= 0) and any other tail elements
__global__ void fill_tail_kernel(float* out, long start, long end) {
    long i = start + (long)blockIdx.x * blockDim.x + threadIdx.x;
    if (i < end) out[i] = 0.f;
}

// ---------------------------------------------------------------------------
extern "C" void kernel_launch(void* const* d_in, const int* in_sizes, int n_in,
                              void* d_out, int out_size) {
    const float* x      = (const float*)d_in[0];
    const int*   nbr    = (const int*)d_in[1];
    const float* gamma1 = (const float*)d_in[2];
    const float* beta1  = (const float*)d_in[3];
    const float* W1     = (const float*)d_in[4];
    const float* gamma2 = (const float*)d_in[5];
    const float* beta2  = (const float*)d_in[6];
    const float* W2     = (const float*)d_in[7];
    const float* Wskip  = (const float*)d_in[8];
    const float* bskip  = (const float*)d_in[9];
    float* out = (float*)d_out;

    int n = in_sizes[0] / 32;
    int nblk = (n + 255) / 256;

    float* h1p = nullptr;
    cudaGetSymbolAddress((void**)&h1p, g_h1);

    // skip path: out = x @ Wskip + bskip  (1x1 conv, no gather/affine/silu)
    conv_kernel<32, 1, false, false, false, false, true>
        <<<nblk, 256>>>(x, nullptr, Wskip, bskip, out, n);

    // GN1 -> conv1 -> SiLU  (into g_h1)
    zero_stats_kernel<<<1, 32>>>();
    gn_reduce_kernel<32><<<1184, 256>>>(x, n);
    gn_finalize_kernel<32><<<1, 64>>>(gamma1, beta1, n);
    conv_kernel<32, 27, true, true, true, false, false>
        <<<nblk, 256>>>(x, nbr, W1, nullptr, h1p, n);

    // GN2 -> conv2 -> SiLU, accumulated into out (which holds skip)
    zero_stats_kernel<<<1, 32>>>();
    gn_reduce_kernel<64><<<1184, 256>>>(h1p, n);
    gn_finalize_kernel<64><<<1, 64>>>(gamma2, beta2, n);
    conv_kernel<64, 27, true, true, true, true, false>
        <<<nblk, 256>>>(h1p, nbr, W2, nullptr, out, n);

    // tail (feat_depth scalar etc.) = 0
    long main_elems = (long)n * 64;
    if ((long)out_size > main_elems) {
        long tail = (long)out_size - main_elems;
        int tb = (int)((tail + 255) / 256);
        fill_tail_kernel<<<tb, 256>>>(out, main_elems, (long)out_size);
    }
}

// round 2
// speedup vs baseline: 1.0364x; 1.0364x over previous
#include <cuda_runtime.h>
#include <math.h>

// Problem constants (shape is fixed by the dataset)
#define NMAX 500000
#define NGROUPS 8

// Scratch (device globals: no allocation allowed in kernel_launch)
__device__ float g_h1[(size_t)NMAX * 64];  // conv1 output (post-SiLU)
__device__ float g_stats[16];              // per-group {sum, sumsq}
__device__ float g_scale[64];              // fused GN affine scale
__device__ float g_bias[64];               // fused GN affine bias

// ---------------------------------------------------------------------------
// Packed fp32x2 helpers (sm_103a FFMA2 — ptxas never auto-generates these)
// ---------------------------------------------------------------------------
__device__ __forceinline__ void ffma2(unsigned long long& d,
                                      unsigned long long a,
                                      unsigned long long b) {
    asm("fma.rn.f32x2 %0, %1, %2, %3;" : "=l"(d) : "l"(a), "l"(b), "l"(d));
}
__device__ __forceinline__ unsigned long long dup2(float x) {
    unsigned long long r;
    asm("mov.b64 %0, {%1, %1};" : "=l"(r) : "f"(x));
    return r;
}
__device__ __forceinline__ float2 unpack2(unsigned long long v) {
    float2 f;
    asm("mov.b64 {%0, %1}, %2;" : "=f"(f.x), "=f"(f.y) : "l"(v));
    return f;
}

// ---------------------------------------------------------------------------
// GroupNorm statistics
// ---------------------------------------------------------------------------
__global__ void zero_stats_kernel() {
    if (threadIdx.x < 16) g_stats[threadIdx.x] = 0.f;
}

template <int C>
__global__ void gn_reduce_kernel(const float* __restrict__ x, int n) {
    constexpr int Q = C / 4;        // float4 per row
    constexpr int CPG = C / NGROUPS;
    int tid = blockIdx.x * blockDim.x + threadIdx.x;
    int total = gridDim.x * blockDim.x;        // multiple of Q by construction
    int q = tid & (Q - 1);                     // fixed per thread
    int g = (q * 4) / CPG;                     // one group per float4
    float s = 0.f, ss = 0.f;
    long nQ = (long)n * Q;
    const float4* xp = (const float4*)x;
    for (long e = tid; e < nQ; e += total) {
        float4 v = xp[e];
        s += (v.x + v.y) + (v.z + v.w);
        ss += v.x * v.x + v.y * v.y + v.z * v.z + v.w * v.w;
    }
    __shared__ float sh[16];
    if (threadIdx.x < 16) sh[threadIdx.x] = 0.f;
    __syncthreads();
    atomicAdd(&sh[2 * g], s);
    atomicAdd(&sh[2 * g + 1], ss);
    __syncthreads();
    if (threadIdx.x < 16) atomicAdd(&g_stats[threadIdx.x], sh[threadIdx.x]);
}

template <int C>
__global__ void gn_finalize_kernel(const float* __restrict__ gamma,
                                   const float* __restrict__ beta, int n) {
    int c = threadIdx.x;
    if (c < C) {
        int g = c / (C / NGROUPS);
        float cnt = (float)n * (C / NGROUPS);
        float mean = g_stats[2 * g] / cnt;
        float var = g_stats[2 * g + 1] / cnt - mean * mean;
        float sc = gamma[c] * rsqrtf(var + 1e-5f);
        g_scale[c] = sc;
        g_bias[c] = beta[c] - mean * sc;
    }
}

// ---------------------------------------------------------------------------
// Gather-conv: out[v, 0:64] (+)= [SiLU]( sum_k affine(x[nbr[v,k]]) @ W[k] ) [+ obias]
// Tile: 256 voxels x 64 outputs per block, 256 threads.
// Per-thread 8x8 tile computed as 4x8 f32x2 FFMA2 (pairs along voxel axis).
// ---------------------------------------------------------------------------
template <int CIN, int KT, bool GATHER, bool AFFINE, bool SILU_EN, bool ACCUM, bool BIAS>
__global__ void __launch_bounds__(256, 2)
conv_kernel(const float* __restrict__ xin,
            const int* __restrict__ nbr,
            const float* __restrict__ W,       // [KT][CIN][64]
            const float* __restrict__ obias,   // [64] or null
            float* __restrict__ out, int n) {
    constexpr int TM = 256;
    constexpr int NCH = CIN / 32;
    __shared__ __align__(16) float As[32][TM + 4];   // channel-major gathered inputs
    __shared__ __align__(16) float Bs[32][64];       // weight chunk
    __shared__ int Nk[TM];

    const int tid = threadIdx.x;
    const int v0 = blockIdx.x * TM;
    const int vv = tid >> 3;           // voxel group 0..31 (8 voxels each)
    const int ov = tid & 7;            // output group: o = ov*4+j and 32+ov*4+j
    const int c4 = (tid & 7) << 2;     // gather channel base within chunk

    unsigned long long acc2[4][8];     // pairs of voxels (i=2p, 2p+1) x 8 outputs
#pragma unroll
    for (int p = 0; p < 4; ++p)
#pragma unroll
        for (int j = 0; j < 8; ++j) acc2[p][j] = 0ull;

    for (int k = 0; k < KT; ++k) {
        {
            int v = v0 + tid;
            int vc = v < n ? v : (n - 1);
            if constexpr (GATHER)
                Nk[tid] = nbr[(long)vc * KT + k];
            else
                Nk[tid] = vc;
        }
        __syncthreads();
#pragma unroll
        for (int ch = 0; ch < NCH; ++ch) {
            const int c0 = ch * 32;
            // stage W[k][c0:c0+32][0:64] into Bs (contiguous copy)
            {
                const float4* Wp = (const float4*)(W + ((long)k * CIN + c0) * 64);
                float4* Bp = (float4*)(&Bs[0][0]);
                Bp[tid] = Wp[tid];
                Bp[tid + 256] = Wp[tid + 256];
            }
            // affine params for this thread's 4 channels
            float s0 = 1.f, s1 = 1.f, s2 = 1.f, s3 = 1.f;
            float b0 = 0.f, b1 = 0.f, b2 = 0.f, b3 = 0.f;
            if constexpr (AFFINE) {
                s0 = g_scale[c0 + c4 + 0]; s1 = g_scale[c0 + c4 + 1];
                s2 = g_scale[c0 + c4 + 2]; s3 = g_scale[c0 + c4 + 3];
                b0 = g_bias[c0 + c4 + 0];  b1 = g_bias[c0 + c4 + 1];
                b2 = g_bias[c0 + c4 + 2];  b3 = g_bias[c0 + c4 + 3];
            }
            // gather 256 rows (transposed into As)
#pragma unroll
            for (int it = 0; it < 8; ++it) {
                int v = it * 32 + (tid >> 3);
                int j = Nk[v];
                float4 xv = *(const float4*)(xin + (long)j * CIN + c0 + c4);
                if constexpr (AFFINE) {
                    xv.x = fmaf(xv.x, s0, b0);
                    xv.y = fmaf(xv.y, s1, b1);
                    xv.z = fmaf(xv.z, s2, b2);
                    xv.w = fmaf(xv.w, s3, b3);
                }
                As[c4 + 0][v] = xv.x;
                As[c4 + 1][v] = xv.y;
                As[c4 + 2][v] = xv.z;
                As[c4 + 3][v] = xv.w;
            }
            __syncthreads();
            // register-tile GEMM over the 32-channel chunk using packed FFMA2
#pragma unroll
            for (int c = 0; c < 32; ++c) {
                // a pairs come naturally packed from 16B shared loads
                ulonglong2 a01 = *(const ulonglong2*)&As[c][vv * 8];
                ulonglong2 a23 = *(const ulonglong2*)&As[c][vv * 8 + 4];
                unsigned long long aa[4] = {a01.x, a01.y, a23.x, a23.y};
                float4 bl = *(const float4*)&Bs[c][ov * 4];
                float4 bh = *(const float4*)&Bs[c][32 + ov * 4];
                unsigned long long bb[8];
                bb[0] = dup2(bl.x); bb[1] = dup2(bl.y);
                bb[2] = dup2(bl.z); bb[3] = dup2(bl.w);
                bb[4] = dup2(bh.x); bb[5] = dup2(bh.y);
                bb[6] = dup2(bh.z); bb[7] = dup2(bh.w);
#pragma unroll
                for (int p = 0; p < 4; ++p)
#pragma unroll
                    for (int j = 0; j < 8; ++j)
                        ffma2(acc2[p][j], aa[p], bb[j]);
            }
            __syncthreads();
        }
    }

    // epilogue
    float ob[8];
#pragma unroll
    for (int j = 0; j < 8; ++j) ob[j] = 0.f;
    if constexpr (BIAS) {
#pragma unroll
        for (int j = 0; j < 4; ++j) {
            ob[j] = obias[ov * 4 + j];
            ob[4 + j] = obias[32 + ov * 4 + j];
        }
    }
#pragma unroll
    for (int p = 0; p < 4; ++p) {
#pragma unroll
        for (int half = 0; half < 2; ++half) {
            int i = 2 * p + half;
            int v = v0 + vv * 8 + i;
            if (v < n) {
                float r[8];
#pragma unroll
                for (int j = 0; j < 8; ++j) {
                    float2 pr = unpack2(acc2[p][j]);
                    float t = half ? pr.y : pr.x;
                    if constexpr (SILU_EN) t = t / (1.f + __expf(-t));
                    r[j] = t + ob[j];
                }
                float* po = out + (long)v * 64 + ov * 4;
                if constexpr (ACCUM) {
                    float4 e0 = *(const float4*)po;
                    float4 e1 = *(const float4*)(po + 32);
                    r[0] += e0.x; r[1] += e0.y; r[2] += e0.z; r[3] += e0.w;
                    r[4] += e1.x; r[5] += e1.y; r[6] += e1.z; r[7] += e1.w;
                }
                *(float4*)po = make_float4(r[0], r[1], r[2], r[3]);
                *(float4*)(po + 32) = make_float4(r[4], r[5], r[6], r[7]);
            }
        }
    }
}

// feat_depth (= 0) and any other tail elements
__global__ void fill_tail_kernel(float* out, long start, long end) {
    long i = start + (long)blockIdx.x * blockDim.x + threadIdx.x;
    if (i < end) out[i] = 0.f;
}

// ---------------------------------------------------------------------------
extern "C" void kernel_launch(void* const* d_in, const int* in_sizes, int n_in,
                              void* d_out, int out_size) {
    const float* x      = (const float*)d_in[0];
    const int*   nbr    = (const int*)d_in[1];
    const float* gamma1 = (const float*)d_in[2];
    const float* beta1  = (const float*)d_in[3];
    const float* W1     = (const float*)d_in[4];
    const float* gamma2 = (const float*)d_in[5];
    const float* beta2  = (const float*)d_in[6];
    const float* W2     = (const float*)d_in[7];
    const float* Wskip  = (const float*)d_in[8];
    const float* bskip  = (const float*)d_in[9];
    float* out = (float*)d_out;

    int n = in_sizes[0] / 32;
    int nblk = (n + 255) / 256;

    float* h1p = nullptr;
    cudaGetSymbolAddress((void**)&h1p, g_h1);

    // skip path: out = x @ Wskip + bskip  (1x1 conv, no gather/affine/silu)
    conv_kernel<32, 1, false, false, false, false, true>
        <<<nblk, 256>>>(x, nullptr, Wskip, bskip, out, n);

    // GN1 -> conv1 -> SiLU  (into g_h1)
    zero_stats_kernel<<<1, 32>>>();
    gn_reduce_kernel<32><<<1184, 256>>>(x, n);
    gn_finalize_kernel<32><<<1, 64>>>(gamma1, beta1, n);
    conv_kernel<32, 27, true, true, true, false, false>
        <<<nblk, 256>>>(x, nbr, W1, nullptr, h1p, n);

    // GN2 -> conv2 -> SiLU, accumulated into out (which holds skip)
    zero_stats_kernel<<<1, 32>>>();
    gn_reduce_kernel<64><<<1184, 256>>>(h1p, n);
    gn_finalize_kernel<64><<<1, 64>>>(gamma2, beta2, n);
    conv_kernel<64, 27, true, true, true, true, false>
        <<<nblk, 256>>>(h1p, nbr, W2, nullptr, out, n);

    // tail (feat_depth scalar etc.) = 0
    long main_elems = (long)n * 64;
    if ((long)out_size > main_elems) {
        long tail = (long)out_size - main_elems;
        int tb = (int)((tail + 255) / 256);
        fill_tail_kernel<<<tb, 256>>>(out, main_elems, (long)out_size);
    }
}

// round 4
// speedup vs baseline: 1.7767x; 1.7143x over previous
#include <cuda_runtime.h>
#include <cuda_bf16.h>
#include <math.h>
#include <stdint.h>

#define NMAX 500000
#define NGROUPS 8
#define KT 27

// ---------------------------------------------------------------------------
// Device global scratch (no allocation allowed in kernel_launch)
// ---------------------------------------------------------------------------
__device__ __nv_bfloat16 g_xraw[(size_t)NMAX * 64];    // per row: [hi c0..31 | lo c0..31] (128B)
__device__ __nv_bfloat16 g_h1raw[(size_t)NMAX * 128];  // per row: [hi c0..63 | lo c0..63] (256B)
__device__ __nv_bfloat16 g_w1t[KT * 64 * 64];          // [k][n][hi c0..31 | lo c0..31]
__device__ __nv_bfloat16 g_w2h[KT * 64 * 64];          // [k][n][c0..63] hi
__device__ __nv_bfloat16 g_w2l[KT * 64 * 64];          // [k][n][c0..63] lo
__device__ float g_bias1[64];
__device__ float g_bias2[64];
__device__ float g_stats[16];
__device__ float g_scale[64];
__device__ float g_bias[64];

// ---------------------------------------------------------------------------
// Helpers
// ---------------------------------------------------------------------------
__device__ __forceinline__ uint32_t smem_to_u32(const void* p) {
    uint32_t a;
    asm("{ .reg .u64 t; cvta.to.shared.u64 t, %1; cvt.u32.u64 %0, t; }" : "=r"(a) : "l"(p));
    return a;
}
__device__ __forceinline__ void sts16(uint32_t addr, uint4 v) {
    asm volatile("st.shared.v4.b32 [%0], {%1,%2,%3,%4};"
                 :: "r"(addr), "r"(v.x), "r"(v.y), "r"(v.z), "r"(v.w) : "memory");
}
__device__ __forceinline__ void ldsm4(uint32_t* r, uint32_t addr) {
    asm volatile("ldmatrix.sync.aligned.m8n8.x4.shared.b16 {%0,%1,%2,%3}, [%4];"
                 : "=r"(r[0]), "=r"(r[1]), "=r"(r[2]), "=r"(r[3]) : "r"(addr));
}
__device__ __forceinline__ void ldsm2(uint32_t* r, uint32_t addr) {
    asm volatile("ldmatrix.sync.aligned.m8n8.x2.shared.b16 {%0,%1}, [%2];"
                 : "=r"(r[0]), "=r"(r[1]) : "r"(addr));
}
__device__ __forceinline__ void mma16816(float* d, const uint32_t* a, const uint32_t* b) {
    asm volatile(
        "mma.sync.aligned.m16n8k16.row.col.f32.bf16.bf16.f32 "
        "{%0,%1,%2,%3}, {%4,%5,%6,%7}, {%8,%9}, {%0,%1,%2,%3};"
        : "+f"(d[0]), "+f"(d[1]), "+f"(d[2]), "+f"(d[3])
        : "r"(a[0]), "r"(a[1]), "r"(a[2]), "r"(a[3]), "r"(b[0]), "r"(b[1]));
}
__device__ __forceinline__ uint32_t pbf2(float e0, float e1) {  // pack [e0(lo), e1(hi)]
    uint32_t r;
    asm("cvt.rn.bf16x2.f32 %0, %1, %2;" : "=r"(r) : "f"(e1), "f"(e0));
    return r;
}
__device__ __forceinline__ uint32_t packbf(__nv_bfloat16 a, __nv_bfloat16 b) {
    __nv_bfloat162 t = __halves2bfloat162(a, b);
    return *reinterpret_cast<uint32_t*>(&t);
}
__device__ __forceinline__ float2 ubf2(uint32_t u) {
    __nv_bfloat162 h = *reinterpret_cast<__nv_bfloat162*>(&u);
    return __bfloat1622float2(h);
}
__device__ __forceinline__ float silu_f(float t) { return t / (1.f + __expf(-t)); }

// ---------------------------------------------------------------------------
// GroupNorm statistics
// ---------------------------------------------------------------------------
__global__ void zero_stats_kernel() {
    if (threadIdx.x < 16) g_stats[threadIdx.x] = 0.f;
    if (threadIdx.x >= 16 && threadIdx.x < 80) g_bias1[threadIdx.x - 16] = 0.f;
    if (threadIdx.x >= 80 && threadIdx.x < 144) g_bias2[threadIdx.x - 80] = 0.f;
}

template <int C>
__global__ void gn_reduce_kernel(const float* __restrict__ x, int n) {
    constexpr int Q = C / 4;
    constexpr int CPG = C / NGROUPS;
    int tid = blockIdx.x * blockDim.x + threadIdx.x;
    int total = gridDim.x * blockDim.x;
    int q = tid & (Q - 1);
    int g = (q * 4) / CPG;
    float s = 0.f, ss = 0.f;
    long nQ = (long)n * Q;
    const float4* xp = (const float4*)x;
    for (long e = tid; e < nQ; e += total) {
        float4 v = xp[e];
        s += (v.x + v.y) + (v.z + v.w);
        ss += v.x * v.x + v.y * v.y + v.z * v.z + v.w * v.w;
    }
    __shared__ float sh[16];
    if (threadIdx.x < 16) sh[threadIdx.x] = 0.f;
    __syncthreads();
    atomicAdd(&sh[2 * g], s);
    atomicAdd(&sh[2 * g + 1], ss);
    __syncthreads();
    if (threadIdx.x < 16) atomicAdd(&g_stats[threadIdx.x], sh[threadIdx.x]);
}

// GN stats over g_h1raw (bf16 hi/lo split rows of 64 channels)
__global__ void gn_reduce_raw_kernel(int n) {
    int tid = blockIdx.x * blockDim.x + threadIdx.x;
    int total = gridDim.x * blockDim.x;
    int sub = tid & 7;                 // channel block = group id (8 ch per group)
    float s = 0.f, ss = 0.f;
    for (long r = tid >> 3; r < n; r += (total >> 3)) {
        const uint4* hp = (const uint4*)(g_h1raw + (size_t)r * 128 + sub * 8);
        const uint4* lp = (const uint4*)(g_h1raw + (size_t)r * 128 + 64 + sub * 8);
        uint4 H = *hp, L = *lp;
        uint32_t hu[4] = {H.x, H.y, H.z, H.w};
        uint32_t lu[4] = {L.x, L.y, L.z, L.w};
#pragma unroll
        for (int j = 0; j < 4; ++j) {
            float2 h2 = ubf2(hu[j]), l2 = ubf2(lu[j]);
            float a = h2.x + l2.x, b = h2.y + l2.y;
            s += a + b;
            ss += a * a + b * b;
        }
    }
    __shared__ float sh[16];
    if (threadIdx.x < 16) sh[threadIdx.x] = 0.f;
    __syncthreads();
    atomicAdd(&sh[2 * sub], s);
    atomicAdd(&sh[2 * sub + 1], ss);
    __syncthreads();
    if (threadIdx.x < 16) atomicAdd(&g_stats[threadIdx.x], sh[threadIdx.x]);
}

template <int C>
__global__ void gn_finalize_kernel(const float* __restrict__ gamma,
                                   const float* __restrict__ beta, int n) {
    int c = threadIdx.x;
    if (c < C) {
        int g = c / (C / NGROUPS);
        float cnt = (float)n * (C / NGROUPS);
        float mean = g_stats[2 * g] / cnt;
        float var = g_stats[2 * g + 1] / cnt - mean * mean;
        float sc = gamma[c] * rsqrtf(var + 1e-5f);
        g_scale[c] = sc;
        g_bias[c] = beta[c] - mean * sc;
    }
}

// ---------------------------------------------------------------------------
// Prep: x (fp32) -> g_xraw bf16 split rows [hi32|lo32]
// ---------------------------------------------------------------------------
__global__ void prep1_kernel(const float* __restrict__ x, int n) {
    int gid = blockIdx.x * blockDim.x + threadIdx.x;
    if (gid >= n * 4) return;
    int v = gid >> 2, q = gid & 3;
    const float4* src = (const float4*)(x + (size_t)v * 32 + q * 8);
    float4 a = src[0], b = src[1];
    float f[8] = {a.x, a.y, a.z, a.w, b.x, b.y, b.z, b.w};
    uint32_t hw[4], lw[4];
#pragma unroll
    for (int j = 0; j < 4; ++j) {
        float f0 = f[2 * j], f1 = f[2 * j + 1];
        __nv_bfloat16 h0 = __float2bfloat16_rn(f0), h1 = __float2bfloat16_rn(f1);
        hw[j] = packbf(h0, h1);
        lw[j] = pbf2(f0 - __bfloat162float(h0), f1 - __bfloat162float(h1));
    }
    char* base = (char*)g_xraw + (size_t)v * 128;
    *(uint4*)(base + q * 16) = *(uint4*)hw;
    *(uint4*)(base + 64 + q * 16) = *(uint4*)lw;
}

// ---------------------------------------------------------------------------
// Weight prep: fold GN scale into W, split to bf16, transpose to [k][n][c];
// accumulate GN-bias contribution into per-output bias vector.
// ---------------------------------------------------------------------------
__global__ void prepW1_kernel(const float* __restrict__ W1) {
    int k = blockIdx.x, nn = threadIdx.x;
    float bs = 0.f;
    for (int c = 0; c < 32; ++c) {
        float w = W1[((size_t)(k * 32 + c)) * 64 + nn];
        bs += g_bias[c] * w;
        float ws = w * g_scale[c];
        __nv_bfloat16 hi = __float2bfloat16_rn(ws);
        g_w1t[((size_t)(k * 64 + nn)) * 64 + c] = hi;
        g_w1t[((size_t)(k * 64 + nn)) * 64 + 32 + c] =
            __float2bfloat16_rn(ws - __bfloat162float(hi));
    }
    atomicAdd(&g_bias1[nn], bs);
}

__global__ void prepW2_kernel(const float* __restrict__ W2) {
    int k = blockIdx.x, nn = threadIdx.x;
    float bs = 0.f;
    for (int c = 0; c < 64; ++c) {
        float w = W2[((size_t)(k * 64 + c)) * 64 + nn];
        bs += g_bias[c] * w;
        float ws = w * g_scale[c];
        __nv_bfloat16 hi = __float2bfloat16_rn(ws);
        g_w2h[((size_t)(k * 64 + nn)) * 64 + c] = hi;
        g_w2l[((size_t)(k * 64 + nn)) * 64 + c] =
            __float2bfloat16_rn(ws - __bfloat162float(hi));
    }
    atomicAdd(&g_bias2[nn], bs);
}

// ---------------------------------------------------------------------------
// mma.sync gather-conv. One CTA = 128 voxels x 64 outputs, 8 warps, each warp
// one m16 slab x all 64 outputs. bf16 hi/lo split, 3 MMA terms -> fp32 acc.
// CONV2=false: CIN=32, combined [hi|lo] rows, output bf16-split to g_h1raw.
// CONV2=true : CIN=64, separate hi/lo tiles, output fp32 += skip in outp.
// SMEM rows are 128B with XOR-16B swizzle (conflict-free ldmatrix).
// ---------------------------------------------------------------------------
template <bool CONV2>
__global__ void __launch_bounds__(256, 2)
mma_conv_kernel(const __nv_bfloat16* __restrict__ Araw,
                const int* __restrict__ nbr,
                const __nv_bfloat16* __restrict__ Bh,
                const __nv_bfloat16* __restrict__ Bl,
                const float* __restrict__ biasv,
                void* __restrict__ outp, int n) {
    constexpr uint32_t A_BYTES = CONV2 ? 32768u : 16384u;  // (2x)128 rows x 128B
    extern __shared__ __align__(1024) char dsmem[];
    float* sbias = (float*)dsmem;
    const uint32_t Abase = smem_to_u32(dsmem + 1024);
    const uint32_t Bbase = Abase + A_BYTES;

    const int tid = threadIdx.x;
    const int w = tid >> 5;
    const int lane = tid & 31;
    const int v0 = blockIdx.x * 128;

    if (tid < 64) sbias[tid] = biasv[tid];

    // gather mapping: 2 threads per row
    const int r = tid >> 1, h = tid & 1;
    const uint32_t rsw = (uint32_t)(r & 7) << 4;

    // ldmatrix lane address components
    const int arow = w * 16 + (lane & 15);
    const uint32_t ahi = (uint32_t)(lane >> 4) << 4;
    const uint32_t asw = (uint32_t)(arow & 7) << 4;
    const uint32_t aoff = Abase + (uint32_t)arow * 128;
    const int brow = lane & 7;
    const uint32_t bhi16 = (uint32_t)((lane >> 3) & 1) << 4;
    const uint32_t bsw = (uint32_t)brow << 4;
    const uint32_t boff = Bbase + (uint32_t)brow * 128;

    float acc[8][4];
#pragma unroll
    for (int i = 0; i < 8; ++i)
#pragma unroll
        for (int j = 0; j < 4; ++j) acc[i][j] = 0.f;

    for (int k = 0; k < KT; ++k) {
        __syncthreads();   // previous tap's reads done before overwrite
        // ---- gather A rows ----
        {
            int vg = v0 + r;
            if (vg >= n) vg = n - 1;
            const int idx = nbr[(long)vg * KT + k];
            if constexpr (CONV2) {
                const uint4* src = (const uint4*)((const char*)Araw + (size_t)idx * 256 + h * 128);
                const uint32_t dst = Abase + (uint32_t)h * 16384u + (uint32_t)r * 128;
#pragma unroll
                for (int i = 0; i < 8; ++i)
                    sts16(dst + (((uint32_t)i * 16) ^ rsw), src[i]);
            } else {
                const uint4* src = (const uint4*)((const char*)Araw + (size_t)idx * 128 + h * 64);
                const uint32_t dst = Abase + (uint32_t)r * 128;
#pragma unroll
                for (int i = 0; i < 4; ++i) {
                    uint32_t ci = (uint32_t)(h * 4 + i) * 16;
                    sts16(dst + (ci ^ rsw), src[i]);
                }
            }
        }
        // ---- stage B tap ----
        if constexpr (CONV2) {
#pragma unroll
            for (int j = 0; j < 4; ++j) {
                int q = tid + j * 256;
                int tile = q >> 9, cc = q & 511, row = cc >> 3, c = cc & 7;
                const uint4* bs = (const uint4*)((tile ? Bl : Bh) + (size_t)k * 4096);
                sts16(Bbase + (uint32_t)tile * 8192u + (uint32_t)row * 128 +
                          (((uint32_t)c * 16) ^ ((uint32_t)(row & 7) << 4)),
                      bs[cc]);
            }
        } else {
#pragma unroll
            for (int j = 0; j < 2; ++j) {
                int q = tid + j * 256;
                int row = q >> 3, c = q & 7;
                const uint4* bs = (const uint4*)(Bh + (size_t)k * 4096);
                sts16(Bbase + (uint32_t)row * 128 +
                          (((uint32_t)c * 16) ^ ((uint32_t)(row & 7) << 4)),
                      bs[q]);
            }
        }
        __syncthreads();
        // ---- compute ----
        if constexpr (CONV2) {
            uint32_t ah[4][4], al[4][4];
#pragma unroll
            for (int kc = 0; kc < 4; ++kc) {
                uint32_t o = (((uint32_t)kc * 32 + ahi) ^ asw);
                ldsm4(ah[kc], aoff + o);
                ldsm4(al[kc], aoff + 16384u + o);
            }
#pragma unroll
            for (int nt = 0; nt < 8; ++nt) {
                const uint32_t bb = boff + (uint32_t)nt * 1024;
#pragma unroll
                for (int kc = 0; kc < 4; ++kc) {
                    uint32_t o = (((uint32_t)kc * 32 + bhi16) ^ bsw);
                    uint32_t bh2[2], bl2[2];
                    ldsm2(bh2, bb + o);
                    ldsm2(bl2, bb + 8192u + o);
                    mma16816(acc[nt], ah[kc], bh2);
                    mma16816(acc[nt], ah[kc], bl2);
                    mma16816(acc[nt], al[kc], bh2);
                }
            }
        } else {
            uint32_t a[4][4];
#pragma unroll
            for (int ck = 0; ck < 4; ++ck)
                ldsm4(a[ck], aoff + (((uint32_t)ck * 32 + ahi) ^ asw));
#pragma unroll
            for (int nt = 0; nt < 8; ++nt) {
                const uint32_t bb = boff + (uint32_t)nt * 1024;
                uint32_t b[4][2];
#pragma unroll
                for (int ck = 0; ck < 4; ++ck)
                    ldsm2(b[ck], bb + (((uint32_t)ck * 32 + bhi16) ^ bsw));
                mma16816(acc[nt], a[0], b[0]);   // Ah*Bh
                mma16816(acc[nt], a[1], b[1]);
                mma16816(acc[nt], a[0], b[2]);   // Ah*Bl
                mma16816(acc[nt], a[1], b[3]);
                mma16816(acc[nt], a[2], b[0]);   // Al*Bh
                mma16816(acc[nt], a[3], b[1]);
            }
        }
    }

    // ---- epilogue ----
    const int g = lane >> 2, tg = lane & 3;
    const int row0 = v0 + w * 16 + g;
#pragma unroll
    for (int half = 0; half < 2; ++half) {
        int v = row0 + half * 8;
        if (v < n) {
            if constexpr (CONV2) {
                float* po = (float*)outp + (size_t)v * 64;
#pragma unroll
                for (int nt = 0; nt < 8; ++nt) {
                    int c = nt * 8 + tg * 2;
                    float2 sk = *(float2*)(po + c);
                    float2 rr;
                    rr.x = silu_f(acc[nt][half * 2 + 0] + sbias[c]) + sk.x;
                    rr.y = silu_f(acc[nt][half * 2 + 1] + sbias[c + 1]) + sk.y;
                    *(float2*)(po + c) = rr;
                }
            } else {
                char* base = (char*)outp + (size_t)v * 256;
#pragma unroll
                for (int nt = 0; nt < 8; ++nt) {
                    int c = nt * 8 + tg * 2;
                    float f0 = silu_f(acc[nt][half * 2 + 0] + sbias[c]);
                    float f1 = silu_f(acc[nt][half * 2 + 1] + sbias[c + 1]);
                    __nv_bfloat16 h0 = __float2bfloat16_rn(f0), h1 = __float2bfloat16_rn(f1);
                    *(uint32_t*)(base + c * 2) = packbf(h0, h1);
                    *(uint32_t*)(base + 128 + c * 2) =
                        pbf2(f0 - __bfloat162float(h0), f1 - __bfloat162float(h1));
                }
            }
        }
    }
}

// ---------------------------------------------------------------------------
// Scalar skip conv (proven): out = x @ Wskip + bskip
// ---------------------------------------------------------------------------
__global__ void __launch_bounds__(256, 2)
skip_kernel(const float* __restrict__ xin,
            const float* __restrict__ W,       // [32][64]
            const float* __restrict__ obias,   // [64]
            float* __restrict__ out, int n) {
    constexpr int TM = 256;
    __shared__ __align__(16) float As[32][TM + 4];
    __shared__ __align__(16) float Bs[32][64];

    const int tid = threadIdx.x;
    const int v0 = blockIdx.x * TM;
    const int vv = tid >> 3;
    const int ov = tid & 7;
    const int c4 = (tid & 7) << 2;

    float acc[8][8];
#pragma unroll
    for (int i = 0; i < 8; ++i)
#pragma unroll
        for (int j = 0; j < 8; ++j) acc[i][j] = 0.f;

    {
        const float4* Wp = (const float4*)W;
        float4* Bp = (float4*)(&Bs[0][0]);
        Bp[tid] = Wp[tid];
        Bp[tid + 256] = Wp[tid + 256];
#pragma unroll
        for (int it = 0; it < 8; ++it) {
            int v = it * 32 + (tid >> 3);
            int j = v0 + v;
            if (j >= n) j = n - 1;
            float4 xv = *(const float4*)(xin + (long)j * 32 + c4);
            As[c4 + 0][v] = xv.x;
            As[c4 + 1][v] = xv.y;
            As[c4 + 2][v] = xv.z;
            As[c4 + 3][v] = xv.w;
        }
        __syncthreads();
#pragma unroll
        for (int c = 0; c < 32; ++c) {
            float a[8], b[8];
            *(float4*)&a[0] = *(const float4*)&As[c][vv * 8];
            *(float4*)&a[4] = *(const float4*)&As[c][vv * 8 + 4];
            *(float4*)&b[0] = *(const float4*)&Bs[c][ov * 4];
            *(float4*)&b[4] = *(const float4*)&Bs[c][32 + ov * 4];
#pragma unroll
            for (int i = 0; i < 8; ++i)
#pragma unroll
                for (int j = 0; j < 8; ++j)
                    acc[i][j] = fmaf(a[i], b[j], acc[i][j]);
        }
    }
    float ob[8];
#pragma unroll
    for (int j = 0; j < 4; ++j) {
        ob[j] = obias[ov * 4 + j];
        ob[4 + j] = obias[32 + ov * 4 + j];
    }
#pragma unroll
    for (int i = 0; i < 8; ++i) {
        int v = v0 + vv * 8 + i;
        if (v < n) {
            float* po = out + (long)v * 64 + ov * 4;
            *(float4*)po = make_float4(acc[i][0] + ob[0], acc[i][1] + ob[1],
                                       acc[i][2] + ob[2], acc[i][3] + ob[3]);
            *(float4*)(po + 32) = make_float4(acc[i][4] + ob[4], acc[i][5] + ob[5],
                                              acc[i][6] + ob[6], acc[i][7] + ob[7]);
        }
    }
}

__global__ void fill_tail_kernel(float* out, long start, long end) {
    long i = start + (long)blockIdx.x * blockDim.x + threadIdx.x;
    if (i < end) out[i] = 0.f;
}

// ---------------------------------------------------------------------------
extern "C" void kernel_launch(void* const* d_in, const int* in_sizes, int n_in,
                              void* d_out, int out_size) {
    const float* x      = (const float*)d_in[0];
    const int*   nbr    = (const int*)d_in[1];
    const float* gamma1 = (const float*)d_in[2];
    const float* beta1  = (const float*)d_in[3];
    const float* W1     = (const float*)d_in[4];
    const float* gamma2 = (const float*)d_in[5];
    const float* beta2  = (const float*)d_in[6];
    const float* W2     = (const float*)d_in[7];
    const float* Wskip  = (const float*)d_in[8];
    const float* bskip  = (const float*)d_in[9];
    float* out = (float*)d_out;

    int n = in_sizes[0] / 32;
    int nblk = (n + 255) / 256;
    int nblk_mma = (n + 127) / 128;

    __nv_bfloat16 *xrawp = nullptr, *h1rawp = nullptr, *w1tp = nullptr,
                  *w2hp = nullptr, *w2lp = nullptr;
    float *b1p = nullptr, *b2p = nullptr;
    cudaGetSymbolAddress((void**)&xrawp, g_xraw);
    cudaGetSymbolAddress((void**)&h1rawp, g_h1raw);
    cudaGetSymbolAddress((void**)&w1tp, g_w1t);
    cudaGetSymbolAddress((void**)&w2hp, g_w2h);
    cudaGetSymbolAddress((void**)&w2lp, g_w2l);
    cudaGetSymbolAddress((void**)&b1p, g_bias1);
    cudaGetSymbolAddress((void**)&b2p, g_bias2);

    const int SMEM1 = 1024 + 16384 + 8192;    // 25600
    const int SMEM2 = 1024 + 32768 + 16384;   // 50176
    cudaFuncSetAttribute(mma_conv_kernel<false>,
                         cudaFuncAttributeMaxDynamicSharedMemorySize, SMEM1);
    cudaFuncSetAttribute(mma_conv_kernel<true>,
                         cudaFuncAttributeMaxDynamicSharedMemorySize, SMEM2);

    // skip path first (conv2 epilogue accumulates onto it)
    skip_kernel<<<nblk, 256>>>(x, Wskip, bskip, out, n);

    // GN1 stats + prep
    zero_stats_kernel<<<1, 160>>>();
    gn_reduce_kernel<32><<<1184, 256>>>(x, n);
    gn_finalize_kernel<32><<<1, 64>>>(gamma1, beta1, n);
    prep1_kernel<<<(n * 4 + 255) / 256, 256>>>(x, n);
    prepW1_kernel<<<KT, 64>>>(W1);

    // conv1 -> g_h1raw (bf16 split, post-SiLU)
    mma_conv_kernel<false><<<nblk_mma, 256, SMEM1>>>(
        xrawp, nbr, w1tp, nullptr, b1p, (void*)h1rawp, n);

    // GN2 stats from split representation
    zero_stats_kernel<<<1, 16>>>();
    gn_reduce_raw_kernel<<<1184, 256>>>(n);
    gn_finalize_kernel<64><<<1, 64>>>(gamma2, beta2, n);
    prepW2_kernel<<<KT, 64>>>(W2);

    // conv2 -> out (accumulates skip)
    mma_conv_kernel<true><<<nblk_mma, 256, SMEM2>>>(
        h1rawp, nbr, w2hp, w2lp, b2p, (void*)out, n);

    long main_elems = (long)n * 64;
    if ((long)out_size > main_elems) {
        long tail = (long)out_size - main_elems;
        int tb = (int)((tail + 255) / 256);
        fill_tail_kernel<<<tb, 256>>>(out, main_elems, (long)out_size);
    }
}

// round 5
// speedup vs baseline: 3.0059x; 1.6919x over previous
#include <cuda_runtime.h>
#include <cuda_fp16.h>
#include <math.h>
#include <stdint.h>

#define NMAX 500000
#define NGROUPS 8
#define KT 27

// ---------------------------------------------------------------------------
// Device global scratch (no allocation allowed in kernel_launch)
// ---------------------------------------------------------------------------
__device__ __half g_xf16[(size_t)NMAX * 32];    // activations conv1, fp16 rows 64B
__device__ __half g_h1f16[(size_t)NMAX * 64];   // conv1 output (post-SiLU), rows 128B
__device__ __half g_w1h[KT * 64 * 32];          // [k][n][c] hi
__device__ __half g_w1l[KT * 64 * 32];          // [k][n][c] lo
__device__ __half g_w2h[KT * 64 * 64];
__device__ __half g_w2l[KT * 64 * 64];
__device__ float g_bias1[64];
__device__ float g_bias2[64];
__device__ float g_stats[16];
__device__ float g_scale[64];
__device__ float g_bias[64];

// ---------------------------------------------------------------------------
// Helpers
// ---------------------------------------------------------------------------
__device__ __forceinline__ uint32_t smem_to_u32(const void* p) {
    uint32_t a;
    asm("{ .reg .u64 t; cvta.to.shared.u64 t, %1; cvt.u32.u64 %0, t; }" : "=r"(a) : "l"(p));
    return a;
}
__device__ __forceinline__ void cp16(uint32_t dst, const void* src) {
    asm volatile("cp.async.cg.shared.global [%0], [%1], 16;" :: "r"(dst), "l"(src));
}
#define CP_COMMIT() asm volatile("cp.async.commit_group;" ::: "memory")
#define CP_WAIT(N) asm volatile("cp.async.wait_group %0;" :: "n"(N) : "memory")

__device__ __forceinline__ void ldsm4(uint32_t* r, uint32_t addr) {
    asm volatile("ldmatrix.sync.aligned.m8n8.x4.shared.b16 {%0,%1,%2,%3}, [%4];"
                 : "=r"(r[0]), "=r"(r[1]), "=r"(r[2]), "=r"(r[3]) : "r"(addr));
}
__device__ __forceinline__ void ldsm2(uint32_t* r, uint32_t addr) {
    asm volatile("ldmatrix.sync.aligned.m8n8.x2.shared.b16 {%0,%1}, [%2];"
                 : "=r"(r[0]), "=r"(r[1]) : "r"(addr));
}
__device__ __forceinline__ void mma16816(float* d, const uint32_t* a, const uint32_t* b) {
    asm volatile(
        "mma.sync.aligned.m16n8k16.row.col.f32.f16.f16.f32 "
        "{%0,%1,%2,%3}, {%4,%5,%6,%7}, {%8,%9}, {%0,%1,%2,%3};"
        : "+f"(d[0]), "+f"(d[1]), "+f"(d[2]), "+f"(d[3])
        : "r"(a[0]), "r"(a[1]), "r"(a[2]), "r"(a[3]), "r"(b[0]), "r"(b[1]));
}
__device__ __forceinline__ float silu_f(float t) { return t / (1.f + __expf(-t)); }

// ---------------------------------------------------------------------------
// GroupNorm statistics
// ---------------------------------------------------------------------------
__global__ void zero_stats_kernel() {
    if (threadIdx.x < 16) g_stats[threadIdx.x] = 0.f;
    if (threadIdx.x >= 16 && threadIdx.x < 80) g_bias1[threadIdx.x - 16] = 0.f;
    if (threadIdx.x >= 80 && threadIdx.x < 144) g_bias2[threadIdx.x - 80] = 0.f;
}

template <int C>
__global__ void gn_reduce_kernel(const float* __restrict__ x, int n) {
    constexpr int Q = C / 4;
    constexpr int CPG = C / NGROUPS;
    int tid = blockIdx.x * blockDim.x + threadIdx.x;
    int total = gridDim.x * blockDim.x;
    int q = tid & (Q - 1);
    int g = (q * 4) / CPG;
    float s = 0.f, ss = 0.f;
    long nQ = (long)n * Q;
    const float4* xp = (const float4*)x;
    for (long e = tid; e < nQ; e += total) {
        float4 v = xp[e];
        s += (v.x + v.y) + (v.z + v.w);
        ss += v.x * v.x + v.y * v.y + v.z * v.z + v.w * v.w;
    }
    __shared__ float sh[16];
    if (threadIdx.x < 16) sh[threadIdx.x] = 0.f;
    __syncthreads();
    atomicAdd(&sh[2 * g], s);
    atomicAdd(&sh[2 * g + 1], ss);
    __syncthreads();
    if (threadIdx.x < 16) atomicAdd(&g_stats[threadIdx.x], sh[threadIdx.x]);
}

// GN stats over g_h1f16 (fp16 rows of 64 channels)
__global__ void gn_reduce_h1_kernel(int n) {
    int tid = blockIdx.x * blockDim.x + threadIdx.x;
    int total = gridDim.x * blockDim.x;
    int sub = tid & 7;                 // 8 channels per group
    float s = 0.f, ss = 0.f;
    for (long r = tid >> 3; r < n; r += (total >> 3)) {
        uint4 H = *(const uint4*)(g_h1f16 + (size_t)r * 64 + sub * 8);
        uint32_t hu[4] = {H.x, H.y, H.z, H.w};
#pragma unroll
        for (int j = 0; j < 4; ++j) {
            __half2 h2 = *reinterpret_cast<__half2*>(&hu[j]);
            float2 f = __half22float2(h2);
            s += f.x + f.y;
            ss += f.x * f.x + f.y * f.y;
        }
    }
    __shared__ float sh[16];
    if (threadIdx.x < 16) sh[threadIdx.x] = 0.f;
    __syncthreads();
    atomicAdd(&sh[2 * sub], s);
    atomicAdd(&sh[2 * sub + 1], ss);
    __syncthreads();
    if (threadIdx.x < 16) atomicAdd(&g_stats[threadIdx.x], sh[threadIdx.x]);
}

template <int C>
__global__ void gn_finalize_kernel(const float* __restrict__ gamma,
                                   const float* __restrict__ beta, int n) {
    int c = threadIdx.x;
    if (c < C) {
        int g = c / (C / NGROUPS);
        float cnt = (float)n * (C / NGROUPS);
        float mean = g_stats[2 * g] / cnt;
        float var = g_stats[2 * g + 1] / cnt - mean * mean;
        float sc = gamma[c] * rsqrtf(var + 1e-5f);
        g_scale[c] = sc;
        g_bias[c] = beta[c] - mean * sc;
    }
}

// ---------------------------------------------------------------------------
// Prep: x (fp32) -> g_xf16 (fp16)
// ---------------------------------------------------------------------------
__global__ void prep1_kernel(const float* __restrict__ x, int n) {
    int gid = blockIdx.x * blockDim.x + threadIdx.x;
    if (gid >= n * 4) return;
    int v = gid >> 2, q = gid & 3;
    const float4* src = (const float4*)(x + (size_t)v * 32 + q * 8);
    float4 a = src[0], b = src[1];
    uint32_t w[4];
    __half2 h;
    h = __floats2half2_rn(a.x, a.y); w[0] = *(uint32_t*)&h;
    h = __floats2half2_rn(a.z, a.w); w[1] = *(uint32_t*)&h;
    h = __floats2half2_rn(b.x, b.y); w[2] = *(uint32_t*)&h;
    h = __floats2half2_rn(b.z, b.w); w[3] = *(uint32_t*)&h;
    *(uint4*)(g_xf16 + (size_t)v * 32 + q * 8) = *(uint4*)w;
}

// ---------------------------------------------------------------------------
// Weight prep: fold GN scale into W, split to fp16 hi/lo, transpose to [k][n][c]
// ---------------------------------------------------------------------------
__global__ void prepW1_kernel(const float* __restrict__ W1) {
    int k = blockIdx.x, nn = threadIdx.x;
    float bs = 0.f;
    for (int c = 0; c < 32; ++c) {
        float w = W1[((size_t)(k * 32 + c)) * 64 + nn];
        bs += g_bias[c] * w;
        float ws = w * g_scale[c];
        __half hi = __float2half_rn(ws);
        g_w1h[((size_t)(k * 64 + nn)) * 32 + c] = hi;
        g_w1l[((size_t)(k * 64 + nn)) * 32 + c] = __float2half_rn(ws - __half2float(hi));
    }
    atomicAdd(&g_bias1[nn], bs);
}

__global__ void prepW2_kernel(const float* __restrict__ W2) {
    int k = blockIdx.x, nn = threadIdx.x;
    float bs = 0.f;
    for (int c = 0; c < 64; ++c) {
        float w = W2[((size_t)(k * 64 + c)) * 64 + nn];
        bs += g_bias[c] * w;
        float ws = w * g_scale[c];
        __half hi = __float2half_rn(ws);
        g_w2h[((size_t)(k * 64 + nn)) * 64 + c] = hi;
        g_w2l[((size_t)(k * 64 + nn)) * 64 + c] = __float2half_rn(ws - __half2float(hi));
    }
    atomicAdd(&g_bias2[nn], bs);
}

// ---------------------------------------------------------------------------
// mma.sync gather-conv, fp16, cp.async double-buffered.
// One CTA = 128 voxels x 64 outputs, 8 warps, warp = one m16 slab x 64 outputs.
// A = activations fp16 (single), B = weights fp16 hi/lo -> 2 MMA terms.
// CONV2=false: CIN=32, rows 64B; output fp16 to g_h1f16.
// CONV2=true : CIN=64, rows 128B; output fp32 += skip in outp.
// ---------------------------------------------------------------------------
template <bool CONV2>
__global__ void __launch_bounds__(256, 2)
mma_conv_kernel(const __half* __restrict__ Araw,
                const int* __restrict__ nbr,
                const __half* __restrict__ Bh,
                const __half* __restrict__ Bl,
                const float* __restrict__ biasv,
                void* __restrict__ outp, int n) {
    constexpr uint32_t A_BYTES = CONV2 ? 16384u : 8192u;  // 128 rows
    constexpr uint32_t B_BYTES = CONV2 ? 16384u : 8192u;  // 2 tiles x 64 rows
    constexpr uint32_t STRIDE = A_BYTES + B_BYTES;

    extern __shared__ __align__(1024) char dsmem[];
    float* sbias = (float*)dsmem;
    const uint32_t base0 = smem_to_u32(dsmem + 1024);

    const int tid = threadIdx.x;
    const int w = tid >> 5;
    const int lane = tid & 31;
    const int v0 = blockIdx.x * 128;

    if (tid < 64) sbias[tid] = biasv[tid];

    const int r = tid >> 1, h = tid & 1;

    // fragment address components
    const int arow = w * 16 + (lane & 15);
    const uint32_t asel = (uint32_t)(lane >> 4);        // k-chunk low/high
    const int brow = lane & 7;
    const uint32_t bsel = (uint32_t)((lane >> 3) & 1);

    float acc[8][4];
#pragma unroll
    for (int i = 0; i < 8; ++i)
#pragma unroll
        for (int j = 0; j < 4; ++j) acc[i][j] = 0.f;

    // stage loader (all cp.async)
    auto load_tap = [&](int k, uint32_t stage) {
        int vg = v0 + r;
        if (vg >= n) vg = n - 1;
        const int idx = nbr[(long)vg * KT + k];
        if constexpr (CONV2) {
            const char* src = (const char*)Araw + (size_t)idx * 128 + h * 64;
            const uint32_t dr = stage + (uint32_t)r * 128;
#pragma unroll
            for (int i = 0; i < 4; ++i) {
                uint32_t c = (uint32_t)(h * 4 + i);
                cp16(dr + (((c ^ ((uint32_t)r & 7)) << 4)), src + i * 16);
            }
#pragma unroll
            for (int j = 0; j < 4; ++j) {
                int q = tid + j * 256;
                int tile = q >> 9, cc = q & 511, row = cc >> 3;
                uint32_t c = (uint32_t)(cc & 7);
                const char* bsrc = (const char*)(tile ? Bl : Bh) + (size_t)k * 8192 + (size_t)cc * 16;
                cp16(stage + A_BYTES + (uint32_t)tile * 8192u + (uint32_t)row * 128 +
                         ((c ^ ((uint32_t)row & 7)) << 4),
                     bsrc);
            }
        } else {
            const char* src = (const char*)Araw + (size_t)idx * 64 + h * 32;
            const uint32_t dr = stage + (uint32_t)r * 64;
#pragma unroll
            for (int i = 0; i < 2; ++i) {
                uint32_t c = (uint32_t)(h * 2 + i);
                cp16(dr + ((c ^ ((uint32_t)r & 3)) << 4), src + i * 16);
            }
#pragma unroll
            for (int j = 0; j < 2; ++j) {
                int q = tid + j * 256;
                int tile = q >> 8, cc = q & 255, row = cc >> 2;
                uint32_t c = (uint32_t)(cc & 3);
                const char* bsrc = (const char*)(tile ? Bl : Bh) + (size_t)k * 4096 + (size_t)cc * 16;
                cp16(stage + A_BYTES + (uint32_t)tile * 4096u + (uint32_t)row * 64 +
                         ((c ^ ((uint32_t)row & 3)) << 4),
                     bsrc);
            }
        }
    };

    // prologue: stage 0 <- tap 0
    load_tap(0, base0);
    CP_COMMIT();

    for (int k = 0; k < KT; ++k) {
        __syncthreads();   // all warps done computing tap k-1 (its stage gets overwritten below)
        if (k + 1 < KT) {
            load_tap(k + 1, base0 + (uint32_t)((k + 1) & 1) * STRIDE);
            CP_COMMIT();
            CP_WAIT(1);    // tap-k group complete
        } else {
            CP_WAIT(0);
        }
        __syncthreads();   // tap-k data visible to all
        const uint32_t Ab = base0 + (uint32_t)(k & 1) * STRIDE;
        const uint32_t Bb = Ab + A_BYTES;
        if constexpr (CONV2) {
            uint32_t a[4][4];
#pragma unroll
            for (int kc = 0; kc < 4; ++kc)
                ldsm4(a[kc], Ab + (uint32_t)arow * 128 +
                                 ((((uint32_t)kc * 2 + asel) ^ ((uint32_t)arow & 7)) << 4));
#pragma unroll
            for (int nt = 0; nt < 8; ++nt) {
#pragma unroll
                for (int kc = 0; kc < 4; ++kc) {
                    uint32_t off = Bb + (uint32_t)nt * 1024 + (uint32_t)brow * 128 +
                                   ((((uint32_t)kc * 2 + bsel) ^ ((uint32_t)brow & 7)) << 4);
                    uint32_t bh2[2], bl2[2];
                    ldsm2(bh2, off);
                    ldsm2(bl2, off + 8192u);
                    mma16816(acc[nt], a[kc], bh2);
                    mma16816(acc[nt], a[kc], bl2);
                }
            }
        } else {
            uint32_t a[2][4];
#pragma unroll
            for (int kc = 0; kc < 2; ++kc)
                ldsm4(a[kc], Ab + (uint32_t)arow * 64 +
                                 ((((uint32_t)kc * 2 + asel) ^ ((uint32_t)arow & 3)) << 4));
#pragma unroll
            for (int nt = 0; nt < 8; ++nt) {
#pragma unroll
                for (int kc = 0; kc < 2; ++kc) {
                    uint32_t off = Bb + (uint32_t)nt * 512 + (uint32_t)brow * 64 +
                                   ((((uint32_t)kc * 2 + bsel) ^ ((uint32_t)brow & 3)) << 4);
                    uint32_t bh2[2], bl2[2];
                    ldsm2(bh2, off);
                    ldsm2(bl2, off + 4096u);
                    mma16816(acc[nt], a[kc], bh2);
                    mma16816(acc[nt], a[kc], bl2);
                }
            }
        }
    }

    // ---- epilogue ----
    const int g = lane >> 2, tg = lane & 3;
    const int row0 = v0 + w * 16 + g;
#pragma unroll
    for (int half = 0; half < 2; ++half) {
        int v = row0 + half * 8;
        if (v < n) {
            if constexpr (CONV2) {
                float* po = (float*)outp + (size_t)v * 64;
#pragma unroll
                for (int nt = 0; nt < 8; ++nt) {
                    int c = nt * 8 + tg * 2;
                    float2 sk = *(float2*)(po + c);
                    float2 rr;
                    rr.x = silu_f(acc[nt][half * 2 + 0] + sbias[c]) + sk.x;
                    rr.y = silu_f(acc[nt][half * 2 + 1] + sbias[c + 1]) + sk.y;
                    *(float2*)(po + c) = rr;
                }
            } else {
                char* basep = (char*)outp + (size_t)v * 128;
#pragma unroll
                for (int nt = 0; nt < 8; ++nt) {
                    int c = nt * 8 + tg * 2;
                    float f0 = silu_f(acc[nt][half * 2 + 0] + sbias[c]);
                    float f1 = silu_f(acc[nt][half * 2 + 1] + sbias[c + 1]);
                    __half2 hh = __floats2half2_rn(f0, f1);
                    *(uint32_t*)(basep + c * 2) = *(uint32_t*)&hh;
                }
            }
        }
    }
}

// ---------------------------------------------------------------------------
// Scalar skip conv (proven): out = x @ Wskip + bskip
// ---------------------------------------------------------------------------
__global__ void __launch_bounds__(256, 2)
skip_kernel(const float* __restrict__ xin,
            const float* __restrict__ W,       // [32][64]
            const float* __restrict__ obias,   // [64]
            float* __restrict__ out, int n) {
    constexpr int TM = 256;
    __shared__ __align__(16) float As[32][TM + 4];
    __shared__ __align__(16) float Bs[32][64];

    const int tid = threadIdx.x;
    const int v0 = blockIdx.x * TM;
    const int vv = tid >> 3;
    const int ov = tid & 7;
    const int c4 = (tid & 7) << 2;

    float acc[8][8];
#pragma unroll
    for (int i = 0; i < 8; ++i)
#pragma unroll
        for (int j = 0; j < 8; ++j) acc[i][j] = 0.f;

    {
        const float4* Wp = (const float4*)W;
        float4* Bp = (float4*)(&Bs[0][0]);
        Bp[tid] = Wp[tid];
        Bp[tid + 256] = Wp[tid + 256];
#pragma unroll
        for (int it = 0; it < 8; ++it) {
            int v = it * 32 + (tid >> 3);
            int j = v0 + v;
            if (j >= n) j = n - 1;
            float4 xv = *(const float4*)(xin + (long)j * 32 + c4);
            As[c4 + 0][v] = xv.x;
            As[c4 + 1][v] = xv.y;
            As[c4 + 2][v] = xv.z;
            As[c4 + 3][v] = xv.w;
        }
        __syncthreads();
#pragma unroll
        for (int c = 0; c < 32; ++c) {
            float a[8], b[8];
            *(float4*)&a[0] = *(const float4*)&As[c][vv * 8];
            *(float4*)&a[4] = *(const float4*)&As[c][vv * 8 + 4];
            *(float4*)&b[0] = *(const float4*)&Bs[c][ov * 4];
            *(float4*)&b[4] = *(const float4*)&Bs[c][32 + ov * 4];
#pragma unroll
            for (int i = 0; i < 8; ++i)
#pragma unroll
                for (int j = 0; j < 8; ++j)
                    acc[i][j] = fmaf(a[i], b[j], acc[i][j]);
        }
    }
    float ob[8];
#pragma unroll
    for (int j = 0; j < 4; ++j) {
        ob[j] = obias[ov * 4 + j];
        ob[4 + j] = obias[32 + ov * 4 + j];
    }
#pragma unroll
    for (int i = 0; i < 8; ++i) {
        int v = v0 + vv * 8 + i;
        if (v < n) {
            float* po = out + (long)v * 64 + ov * 4;
            *(float4*)po = make_float4(acc[i][0] + ob[0], acc[i][1] + ob[1],
                                       acc[i][2] + ob[2], acc[i][3] + ob[3]);
            *(float4*)(po + 32) = make_float4(acc[i][4] + ob[4], acc[i][5] + ob[5],
                                              acc[i][6] + ob[6], acc[i][7] + ob[7]);
        }
    }
}

__global__ void fill_tail_kernel(float* out, long start, long end) {
    long i = start + (long)blockIdx.x * blockDim.x + threadIdx.x;
    if (i < end) out[i] = 0.f;
}

// ---------------------------------------------------------------------------
extern "C" void kernel_launch(void* const* d_in, const int* in_sizes, int n_in,
                              void* d_out, int out_size) {
    const float* x      = (const float*)d_in[0];
    const int*   nbr    = (const int*)d_in[1];
    const float* gamma1 = (const float*)d_in[2];
    const float* beta1  = (const float*)d_in[3];
    const float* W1     = (const float*)d_in[4];
    const float* gamma2 = (const float*)d_in[5];
    const float* beta2  = (const float*)d_in[6];
    const float* W2     = (const float*)d_in[7];
    const float* Wskip  = (const float*)d_in[8];
    const float* bskip  = (const float*)d_in[9];
    float* out = (float*)d_out;

    int n = in_sizes[0] / 32;
    int nblk = (n + 255) / 256;
    int nblk_mma = (n + 127) / 128;

    __half *xf16p = nullptr, *h1p = nullptr, *w1hp = nullptr, *w1lp = nullptr,
           *w2hp = nullptr, *w2lp = nullptr;
    float *b1p = nullptr, *b2p = nullptr;
    cudaGetSymbolAddress((void**)&xf16p, g_xf16);
    cudaGetSymbolAddress((void**)&h1p, g_h1f16);
    cudaGetSymbolAddress((void**)&w1hp, g_w1h);
    cudaGetSymbolAddress((void**)&w1lp, g_w1l);
    cudaGetSymbolAddress((void**)&w2hp, g_w2h);
    cudaGetSymbolAddress((void**)&w2lp, g_w2l);
    cudaGetSymbolAddress((void**)&b1p, g_bias1);
    cudaGetSymbolAddress((void**)&b2p, g_bias2);

    const int SMEM1 = 1024 + 2 * (8192 + 8192);     // 33792
    const int SMEM2 = 1024 + 2 * (16384 + 16384);   // 66560
    cudaFuncSetAttribute(mma_conv_kernel<false>,
                         cudaFuncAttributeMaxDynamicSharedMemorySize, SMEM1);
    cudaFuncSetAttribute(mma_conv_kernel<true>,
                         cudaFuncAttributeMaxDynamicSharedMemorySize, SMEM2);

    // skip path first (conv2 epilogue accumulates onto it)
    skip_kernel<<<nblk, 256>>>(x, Wskip, bskip, out, n);

    // GN1 stats + prep
    zero_stats_kernel<<<1, 160>>>();
    gn_reduce_kernel<32><<<1184, 256>>>(x, n);
    gn_finalize_kernel<32><<<1, 64>>>(gamma1, beta1, n);
    prep1_kernel<<<(n * 4 + 255) / 256, 256>>>(x, n);
    prepW1_kernel<<<KT, 64>>>(W1);

    // conv1 -> g_h1f16 (fp16, post-SiLU)
    mma_conv_kernel<false><<<nblk_mma, 256, SMEM1>>>(
        xf16p, nbr, w1hp, w1lp, b1p, (void*)h1p, n);

    // GN2 stats from fp16 h1
    zero_stats_kernel<<<1, 16>>>();
    gn_reduce_h1_kernel<<<1184, 256>>>(n);
    gn_finalize_kernel<64><<<1, 64>>>(gamma2, beta2, n);
    prepW2_kernel<<<KT, 64>>>(W2);

    // conv2 -> out (accumulates skip)
    mma_conv_kernel<true><<<nblk_mma, 256, SMEM2>>>(
        h1p, nbr, w2hp, w2lp, b2p, (void*)out, n);

    long main_elems = (long)n * 64;
    if ((long)out_size > main_elems) {
        long tail = (long)out_size - main_elems;
        int tb = (int)((tail + 255) / 256);
        fill_tail_kernel<<<tb, 256>>>(out, main_elems, (long)out_size);
    }
}

// round 6
// speedup vs baseline: 3.9633x; 1.3185x over previous
#include <cuda_runtime.h>
#include <cuda_fp16.h>
#include <math.h>
#include <stdint.h>

#define NMAX 500000
#define NGROUPS 8
#define KT 27

// ---------------------------------------------------------------------------
// Device global scratch (no allocation allowed in kernel_launch)
// ---------------------------------------------------------------------------
__device__ __half g_xf16[(size_t)NMAX * 32];    // activations conv1, fp16 rows 64B
__device__ __half g_h1f16[(size_t)NMAX * 64];   // conv1 output (post-SiLU), rows 128B
__device__ __half g_w1[KT * 64 * 32];           // [k][n][c]
__device__ __half g_w2[KT * 64 * 64];           // [k][n][c]
__device__ float g_bias1[64];
__device__ float g_bias2[64];
__device__ float g_stats[16];
__device__ float g_scale[64];
__device__ float g_bias[64];

// ---------------------------------------------------------------------------
// Helpers
// ---------------------------------------------------------------------------
__device__ __forceinline__ uint32_t smem_to_u32(const void* p) {
    uint32_t a;
    asm("{ .reg .u64 t; cvta.to.shared.u64 t, %1; cvt.u32.u64 %0, t; }" : "=r"(a) : "l"(p));
    return a;
}
__device__ __forceinline__ void cp16(uint32_t dst, const void* src) {
    asm volatile("cp.async.cg.shared.global [%0], [%1], 16;" :: "r"(dst), "l"(src));
}
#define CP_COMMIT() asm volatile("cp.async.commit_group;" ::: "memory")
#define CP_WAIT(N) asm volatile("cp.async.wait_group %0;" :: "n"(N) : "memory")

__device__ __forceinline__ void ldsm4(uint32_t* r, uint32_t addr) {
    asm volatile("ldmatrix.sync.aligned.m8n8.x4.shared.b16 {%0,%1,%2,%3}, [%4];"
                 : "=r"(r[0]), "=r"(r[1]), "=r"(r[2]), "=r"(r[3]) : "r"(addr));
}
__device__ __forceinline__ void ldsm2(uint32_t* r, uint32_t addr) {
    asm volatile("ldmatrix.sync.aligned.m8n8.x2.shared.b16 {%0,%1}, [%2];"
                 : "=r"(r[0]), "=r"(r[1]) : "r"(addr));
}
__device__ __forceinline__ void mma16816(float* d, const uint32_t* a, const uint32_t* b) {
    asm volatile(
        "mma.sync.aligned.m16n8k16.row.col.f32.f16.f16.f32 "
        "{%0,%1,%2,%3}, {%4,%5,%6,%7}, {%8,%9}, {%0,%1,%2,%3};"
        : "+f"(d[0]), "+f"(d[1]), "+f"(d[2]), "+f"(d[3])
        : "r"(a[0]), "r"(a[1]), "r"(a[2]), "r"(a[3]), "r"(b[0]), "r"(b[1]));
}
__device__ __forceinline__ float silu_f(float t) { return t / (1.f + __expf(-t)); }

// ---------------------------------------------------------------------------
// GroupNorm statistics
// ---------------------------------------------------------------------------
__global__ void zero_stats_kernel() {
    if (threadIdx.x < 16) g_stats[threadIdx.x] = 0.f;
    if (threadIdx.x >= 16 && threadIdx.x < 80) g_bias1[threadIdx.x - 16] = 0.f;
    if (threadIdx.x >= 80 && threadIdx.x < 144) g_bias2[threadIdx.x - 80] = 0.f;
}

template <int C>
__global__ void gn_reduce_kernel(const float* __restrict__ x, int n) {
    constexpr int Q = C / 4;
    constexpr int CPG = C / NGROUPS;
    int tid = blockIdx.x * blockDim.x + threadIdx.x;
    int total = gridDim.x * blockDim.x;
    int q = tid & (Q - 1);
    int g = (q * 4) / CPG;
    float s = 0.f, ss = 0.f;
    long nQ = (long)n * Q;
    const float4* xp = (const float4*)x;
    for (long e = tid; e < nQ; e += total) {
        float4 v = xp[e];
        s += (v.x + v.y) + (v.z + v.w);
        ss += v.x * v.x + v.y * v.y + v.z * v.z + v.w * v.w;
    }
    __shared__ float sh[16];
    if (threadIdx.x < 16) sh[threadIdx.x] = 0.f;
    __syncthreads();
    atomicAdd(&sh[2 * g], s);
    atomicAdd(&sh[2 * g + 1], ss);
    __syncthreads();
    if (threadIdx.x < 16) atomicAdd(&g_stats[threadIdx.x], sh[threadIdx.x]);
}

// GN stats over g_h1f16 (fp16 rows of 64 channels)
__global__ void gn_reduce_h1_kernel(int n) {
    int tid = blockIdx.x * blockDim.x + threadIdx.x;
    int total = gridDim.x * blockDim.x;
    int sub = tid & 7;                 // 8 channels per group
    float s = 0.f, ss = 0.f;
    for (long r = tid >> 3; r < n; r += (total >> 3)) {
        uint4 H = *(const uint4*)(g_h1f16 + (size_t)r * 64 + sub * 8);
        uint32_t hu[4] = {H.x, H.y, H.z, H.w};
#pragma unroll
        for (int j = 0; j < 4; ++j) {
            __half2 h2 = *reinterpret_cast<__half2*>(&hu[j]);
            float2 f = __half22float2(h2);
            s += f.x + f.y;
            ss += f.x * f.x + f.y * f.y;
        }
    }
    __shared__ float sh[16];
    if (threadIdx.x < 16) sh[threadIdx.x] = 0.f;
    __syncthreads();
    atomicAdd(&sh[2 * sub], s);
    atomicAdd(&sh[2 * sub + 1], ss);
    __syncthreads();
    if (threadIdx.x < 16) atomicAdd(&g_stats[threadIdx.x], sh[threadIdx.x]);
}

template <int C>
__global__ void gn_finalize_kernel(const float* __restrict__ gamma,
                                   const float* __restrict__ beta, int n) {
    int c = threadIdx.x;
    if (c < C) {
        int g = c / (C / NGROUPS);
        float cnt = (float)n * (C / NGROUPS);
        float mean = g_stats[2 * g] / cnt;
        float var = g_stats[2 * g + 1] / cnt - mean * mean;
        float sc = gamma[c] * rsqrtf(var + 1e-5f);
        g_scale[c] = sc;
        g_bias[c] = beta[c] - mean * sc;
    }
}

// ---------------------------------------------------------------------------
// Prep: x (fp32) -> g_xf16 (fp16)
// ---------------------------------------------------------------------------
__global__ void prep1_kernel(const float* __restrict__ x, int n) {
    int gid = blockIdx.x * blockDim.x + threadIdx.x;
    if (gid >= n * 4) return;
    int v = gid >> 2, q = gid & 3;
    const float4* src = (const float4*)(x + (size_t)v * 32 + q * 8);
    float4 a = src[0], b = src[1];
    uint32_t w[4];
    __half2 h;
    h = __floats2half2_rn(a.x, a.y); w[0] = *(uint32_t*)&h;
    h = __floats2half2_rn(a.z, a.w); w[1] = *(uint32_t*)&h;
    h = __floats2half2_rn(b.x, b.y); w[2] = *(uint32_t*)&h;
    h = __floats2half2_rn(b.z, b.w); w[3] = *(uint32_t*)&h;
    *(uint4*)(g_xf16 + (size_t)v * 32 + q * 8) = *(uint4*)w;
}

// ---------------------------------------------------------------------------
// Weight prep: fold GN scale into W, fp16, transpose to [k][n][c]
// ---------------------------------------------------------------------------
__global__ void prepW1_kernel(const float* __restrict__ W1) {
    int k = blockIdx.x, nn = threadIdx.x;
    float bs = 0.f;
    for (int c = 0; c < 32; ++c) {
        float w = W1[((size_t)(k * 32 + c)) * 64 + nn];
        bs += g_bias[c] * w;
        g_w1[((size_t)(k * 64 + nn)) * 32 + c] = __float2half_rn(w * g_scale[c]);
    }
    atomicAdd(&g_bias1[nn], bs);
}

__global__ void prepW2_kernel(const float* __restrict__ W2) {
    int k = blockIdx.x, nn = threadIdx.x;
    float bs = 0.f;
    for (int c = 0; c < 64; ++c) {
        float w = W2[((size_t)(k * 64 + c)) * 64 + nn];
        bs += g_bias[c] * w;
        g_w2[((size_t)(k * 64 + nn)) * 64 + c] = __float2half_rn(w * g_scale[c]);
    }
    atomicAdd(&g_bias2[nn], bs);
}

// ---------------------------------------------------------------------------
// mma.sync gather-conv, fp16 x fp16, cp.async 3-stage pipeline.
// One CTA = 128 voxels x 64 outputs, 8 warps, warp = one m16 slab x 64 outputs.
// CONV2=false: CIN=32, rows 64B; output fp16 to g_h1f16.
// CONV2=true : CIN=64, rows 128B; output fp32 += skip in outp.
// ---------------------------------------------------------------------------
template <bool CONV2>
__global__ void __launch_bounds__(256, 2)
mma_conv_kernel(const __half* __restrict__ Araw,
                const int* __restrict__ nbr,
                const __half* __restrict__ Bw,
                const float* __restrict__ biasv,
                void* __restrict__ outp, int n) {
    constexpr uint32_t A_BYTES = CONV2 ? 16384u : 8192u;  // 128 rows
    constexpr uint32_t B_BYTES = CONV2 ? 8192u : 4096u;   // 64 rows
    constexpr uint32_t STRIDE = A_BYTES + B_BYTES;

    extern __shared__ __align__(1024) char dsmem[];
    float* sbias = (float*)dsmem;
    const uint32_t base0 = smem_to_u32(dsmem + 1024);

    const int tid = threadIdx.x;
    const int w = tid >> 5;
    const int lane = tid & 31;
    const int v0 = blockIdx.x * 128;

    if (tid < 64) sbias[tid] = biasv[tid];

    const int r = tid >> 1, h = tid & 1;

    // fragment address components
    const int arow = w * 16 + (lane & 15);
    const uint32_t asel = (uint32_t)(lane >> 4);        // k-chunk low/high
    const int brow = lane & 7;
    const uint32_t bsel = (uint32_t)((lane >> 3) & 1);

    float acc[8][4];
#pragma unroll
    for (int i = 0; i < 8; ++i)
#pragma unroll
        for (int j = 0; j < 4; ++j) acc[i][j] = 0.f;

    // stage loader (all cp.async)
    auto load_tap = [&](int k, uint32_t stage) {
        int vg = v0 + r;
        if (vg >= n) vg = n - 1;
        const int idx = nbr[(long)vg * KT + k];
        if constexpr (CONV2) {
            const char* src = (const char*)Araw + (size_t)idx * 128 + h * 64;
            const uint32_t dr = stage + (uint32_t)r * 128;
#pragma unroll
            for (int i = 0; i < 4; ++i) {
                uint32_t c = (uint32_t)(h * 4 + i);
                cp16(dr + (((c ^ ((uint32_t)r & 7)) << 4)), src + i * 16);
            }
#pragma unroll
            for (int j = 0; j < 2; ++j) {
                int q = tid + j * 256;               // 512 chunks of 16B
                int row = q >> 3;
                uint32_t c = (uint32_t)(q & 7);
                const char* bsrc = (const char*)Bw + (size_t)k * 8192 + (size_t)q * 16;
                cp16(stage + A_BYTES + (uint32_t)row * 128 +
                         ((c ^ ((uint32_t)row & 7)) << 4),
                     bsrc);
            }
        } else {
            const char* src = (const char*)Araw + (size_t)idx * 64 + h * 32;
            const uint32_t dr = stage + (uint32_t)r * 64;
#pragma unroll
            for (int i = 0; i < 2; ++i) {
                uint32_t c = (uint32_t)(h * 2 + i);
                cp16(dr + ((c ^ ((uint32_t)r & 3)) << 4), src + i * 16);
            }
            {
                int q = tid;                          // 256 chunks of 16B
                int row = q >> 2;
                uint32_t c = (uint32_t)(q & 3);
                const char* bsrc = (const char*)Bw + (size_t)k * 4096 + (size_t)q * 16;
                cp16(stage + A_BYTES + (uint32_t)row * 64 +
                         ((c ^ ((uint32_t)row & 3)) << 4),
                     bsrc);
            }
        }
    };

    // prologue: load taps 0 and 1
    load_tap(0, base0);
    CP_COMMIT();
    load_tap(1, base0 + STRIDE);
    CP_COMMIT();

    for (int k = 0; k < KT; ++k) {
        if (k + 2 < KT) {
            load_tap(k + 2, base0 + (uint32_t)((k + 2) % 3) * STRIDE);
            CP_COMMIT();
            CP_WAIT(2);    // tap-k group complete
        } else if (k + 1 < KT) {
            CP_WAIT(1);
        } else {
            CP_WAIT(0);
        }
        __syncthreads();   // tap-k data visible to all
        const uint32_t Ab = base0 + (uint32_t)(k % 3) * STRIDE;
        const uint32_t Bb = Ab + A_BYTES;
        if constexpr (CONV2) {
            uint32_t a[4][4];
#pragma unroll
            for (int kc = 0; kc < 4; ++kc)
                ldsm4(a[kc], Ab + (uint32_t)arow * 128 +
                                 ((((uint32_t)kc * 2 + asel) ^ ((uint32_t)arow & 7)) << 4));
#pragma unroll
            for (int nt = 0; nt < 8; ++nt) {
#pragma unroll
                for (int kc = 0; kc < 4; ++kc) {
                    uint32_t b2[2];
                    ldsm2(b2, Bb + (uint32_t)nt * 1024 + (uint32_t)brow * 128 +
                                  ((((uint32_t)kc * 2 + bsel) ^ ((uint32_t)brow & 7)) << 4));
                    mma16816(acc[nt], a[kc], b2);
                }
            }
        } else {
            uint32_t a[2][4];
#pragma unroll
            for (int kc = 0; kc < 2; ++kc)
                ldsm4(a[kc], Ab + (uint32_t)arow * 64 +
                                 ((((uint32_t)kc * 2 + asel) ^ ((uint32_t)arow & 3)) << 4));
#pragma unroll
            for (int nt = 0; nt < 8; ++nt) {
#pragma unroll
                for (int kc = 0; kc < 2; ++kc) {
                    uint32_t b2[2];
                    ldsm2(b2, Bb + (uint32_t)nt * 512 + (uint32_t)brow * 64 +
                                  ((((uint32_t)kc * 2 + bsel) ^ ((uint32_t)brow & 3)) << 4));
                    mma16816(acc[nt], a[kc], b2);
                }
            }
        }
        __syncthreads();   // all warps done with tap k before its stage is reloaded
    }

    // ---- epilogue ----
    const int g = lane >> 2, tg = lane & 3;
    const int row0 = v0 + w * 16 + g;
#pragma unroll
    for (int half = 0; half < 2; ++half) {
        int v = row0 + half * 8;
        if (v < n) {
            if constexpr (CONV2) {
                float* po = (float*)outp + (size_t)v * 64;
#pragma unroll
                for (int nt = 0; nt < 8; ++nt) {
                    int c = nt * 8 + tg * 2;
                    float2 sk = *(float2*)(po + c);
                    float2 rr;
                    rr.x = silu_f(acc[nt][half * 2 + 0] + sbias[c]) + sk.x;
                    rr.y = silu_f(acc[nt][half * 2 + 1] + sbias[c + 1]) + sk.y;
                    *(float2*)(po + c) = rr;
                }
            } else {
                char* basep = (char*)outp + (size_t)v * 128;
#pragma unroll
                for (int nt = 0; nt < 8; ++nt) {
                    int c = nt * 8 + tg * 2;
                    float f0 = silu_f(acc[nt][half * 2 + 0] + sbias[c]);
                    float f1 = silu_f(acc[nt][half * 2 + 1] + sbias[c + 1]);
                    __half2 hh = __floats2half2_rn(f0, f1);
                    *(uint32_t*)(basep + c * 2) = *(uint32_t*)&hh;
                }
            }
        }
    }
}

// ---------------------------------------------------------------------------
// Scalar skip conv (proven): out = x @ Wskip + bskip
// ---------------------------------------------------------------------------
__global__ void __launch_bounds__(256, 2)
skip_kernel(const float* __restrict__ xin,
            const float* __restrict__ W,       // [32][64]
            const float* __restrict__ obias,   // [64]
            float* __restrict__ out, int n) {
    constexpr int TM = 256;
    __shared__ __align__(16) float As[32][TM + 4];
    __shared__ __align__(16) float Bs[32][64];

    const int tid = threadIdx.x;
    const int v0 = blockIdx.x * TM;
    const int vv = tid >> 3;
    const int ov = tid & 7;
    const int c4 = (tid & 7) << 2;

    float acc[8][8];
#pragma unroll
    for (int i = 0; i < 8; ++i)
#pragma unroll
        for (int j = 0; j < 8; ++j) acc[i][j] = 0.f;

    {
        const float4* Wp = (const float4*)W;
        float4* Bp = (float4*)(&Bs[0][0]);
        Bp[tid] = Wp[tid];
        Bp[tid + 256] = Wp[tid + 256];
#pragma unroll
        for (int it = 0; it < 8; ++it) {
            int v = it * 32 + (tid >> 3);
            int j = v0 + v;
            if (j >= n) j = n - 1;
            float4 xv = *(const float4*)(xin + (long)j * 32 + c4);
            As[c4 + 0][v] = xv.x;
            As[c4 + 1][v] = xv.y;
            As[c4 + 2][v] = xv.z;
            As[c4 + 3][v] = xv.w;
        }
        __syncthreads();
#pragma unroll
        for (int c = 0; c < 32; ++c) {
            float a[8], b[8];
            *(float4*)&a[0] = *(const float4*)&As[c][vv * 8];
            *(float4*)&a[4] = *(const float4*)&As[c][vv * 8 + 4];
            *(float4*)&b[0] = *(const float4*)&Bs[c][ov * 4];
            *(float4*)&b[4] = *(const float4*)&Bs[c][32 + ov * 4];
#pragma unroll
            for (int i = 0; i < 8; ++i)
#pragma unroll
                for (int j = 0; j < 8; ++j)
                    acc[i][j] = fmaf(a[i], b[j], acc[i][j]);
        }
    }
    float ob[8];
#pragma unroll
    for (int j = 0; j < 4; ++j) {
        ob[j] = obias[ov * 4 + j];
        ob[4 + j] = obias[32 + ov * 4 + j];
    }
#pragma unroll
    for (int i = 0; i < 8; ++i) {
        int v = v0 + vv * 8 + i;
        if (v < n) {
            float* po = out + (long)v * 64 + ov * 4;
            *(float4*)po = make_float4(acc[i][0] + ob[0], acc[i][1] + ob[1],
                                       acc[i][2] + ob[2], acc[i][3] + ob[3]);
            *(float4*)(po + 32) = make_float4(acc[i][4] + ob[4], acc[i][5] + ob[5],
                                              acc[i][6] + ob[6], acc[i][7] + ob[7]);
        }
    }
}

__global__ void fill_tail_kernel(float* out, long start, long end) {
    long i = start + (long)blockIdx.x * blockDim.x + threadIdx.x;
    if (i < end) out[i] = 0.f;
}

// ---------------------------------------------------------------------------
extern "C" void kernel_launch(void* const* d_in, const int* in_sizes, int n_in,
                              void* d_out, int out_size) {
    const float* x      = (const float*)d_in[0];
    const int*   nbr    = (const int*)d_in[1];
    const float* gamma1 = (const float*)d_in[2];
    const float* beta1  = (const float*)d_in[3];
    const float* W1     = (const float*)d_in[4];
    const float* gamma2 = (const float*)d_in[5];
    const float* beta2  = (const float*)d_in[6];
    const float* W2     = (const float*)d_in[7];
    const float* Wskip  = (const float*)d_in[8];
    const float* bskip  = (const float*)d_in[9];
    float* out = (float*)d_out;

    int n = in_sizes[0] / 32;
    int nblk = (n + 255) / 256;
    int nblk_mma = (n + 127) / 128;

    __half *xf16p = nullptr, *h1p = nullptr, *w1p = nullptr, *w2p = nullptr;
    float *b1p = nullptr, *b2p = nullptr;
    cudaGetSymbolAddress((void**)&xf16p, g_xf16);
    cudaGetSymbolAddress((void**)&h1p, g_h1f16);
    cudaGetSymbolAddress((void**)&w1p, g_w1);
    cudaGetSymbolAddress((void**)&w2p, g_w2);
    cudaGetSymbolAddress((void**)&b1p, g_bias1);
    cudaGetSymbolAddress((void**)&b2p, g_bias2);

    const int SMEM1 = 1024 + 3 * (8192 + 4096);     // 37888
    const int SMEM2 = 1024 + 3 * (16384 + 8192);    // 74752
    cudaFuncSetAttribute(mma_conv_kernel<false>,
                         cudaFuncAttributeMaxDynamicSharedMemorySize, SMEM1);
    cudaFuncSetAttribute(mma_conv_kernel<true>,
                         cudaFuncAttributeMaxDynamicSharedMemorySize, SMEM2);

    // skip path first (conv2 epilogue accumulates onto it)
    skip_kernel<<<nblk, 256>>>(x, Wskip, bskip, out, n);

    // GN1 stats + prep
    zero_stats_kernel<<<1, 160>>>();
    gn_reduce_kernel<32><<<1184, 256>>>(x, n);
    gn_finalize_kernel<32><<<1, 64>>>(gamma1, beta1, n);
    prep1_kernel<<<(n * 4 + 255) / 256, 256>>>(x, n);
    prepW1_kernel<<<KT, 64>>>(W1);

    // conv1 -> g_h1f16 (fp16, post-SiLU)
    mma_conv_kernel<false><<<nblk_mma, 256, SMEM1>>>(
        xf16p, nbr, w1p, b1p, (void*)h1p, n);

    // GN2 stats from fp16 h1
    zero_stats_kernel<<<1, 16>>>();
    gn_reduce_h1_kernel<<<1184, 256>>>(n);
    gn_finalize_kernel<64><<<1, 64>>>(gamma2, beta2, n);
    prepW2_kernel<<<KT, 64>>>(W2);

    // conv2 -> out (accumulates skip)
    mma_conv_kernel<true><<<nblk_mma, 256, SMEM2>>>(
        h1p, nbr, w2p, b2p, (void*)out, n);

    long main_elems = (long)n * 64;
    if ((long)out_size > main_elems) {
        long tail = (long)out_size - main_elems;
        int tb = (int)((tail + 255) / 256);
        fill_tail_kernel<<<tb, 256>>>(out, main_elems, (long)out_size);
    }
}

// round 7
// speedup vs baseline: 4.1150x; 1.0383x over previous
#include <cuda_runtime.h>
#include <cuda_fp16.h>
#include <math.h>
#include <stdint.h>

#define NMAX 500000
#define NGROUPS 8
#define KT 27

// ---------------------------------------------------------------------------
// Device global scratch (no allocation allowed in kernel_launch)
// ---------------------------------------------------------------------------
__device__ __half g_xf16[(size_t)NMAX * 32];    // activations conv1, fp16 rows 64B
__device__ __half g_h1f16[(size_t)NMAX * 64];   // conv1 output (post-SiLU), rows 128B
__device__ __half g_w1[KT * 64 * 32];           // [k][n][c]
__device__ __half g_w2[KT * 64 * 64];           // [k][n][c]
__device__ float g_bias1[64];
__device__ float g_bias2[64];
__device__ float g_stats[16];
__device__ float g_scale[64];
__device__ float g_bias[64];

// ---------------------------------------------------------------------------
// Helpers
// ---------------------------------------------------------------------------
__device__ __forceinline__ uint32_t smem_to_u32(const void* p) {
    uint32_t a;
    asm("{ .reg .u64 t; cvta.to.shared.u64 t, %1; cvt.u32.u64 %0, t; }" : "=r"(a) : "l"(p));
    return a;
}
__device__ __forceinline__ void cp16(uint32_t dst, const void* src) {
    asm volatile("cp.async.cg.shared.global [%0], [%1], 16;" :: "r"(dst), "l"(src));
}
#define CP_COMMIT() asm volatile("cp.async.commit_group;" ::: "memory")
#define CP_WAIT(N) asm volatile("cp.async.wait_group %0;" :: "n"(N) : "memory")

__device__ __forceinline__ void ldsm4(uint32_t* r, uint32_t addr) {
    asm volatile("ldmatrix.sync.aligned.m8n8.x4.shared.b16 {%0,%1,%2,%3}, [%4];"
                 : "=r"(r[0]), "=r"(r[1]), "=r"(r[2]), "=r"(r[3]) : "r"(addr));
}
__device__ __forceinline__ void ldsm2(uint32_t* r, uint32_t addr) {
    asm volatile("ldmatrix.sync.aligned.m8n8.x2.shared.b16 {%0,%1}, [%2];"
                 : "=r"(r[0]), "=r"(r[1]) : "r"(addr));
}
__device__ __forceinline__ void mma16816(float* d, const uint32_t* a, const uint32_t* b) {
    asm volatile(
        "mma.sync.aligned.m16n8k16.row.col.f32.f16.f16.f32 "
        "{%0,%1,%2,%3}, {%4,%5,%6,%7}, {%8,%9}, {%0,%1,%2,%3};"
        : "+f"(d[0]), "+f"(d[1]), "+f"(d[2]), "+f"(d[3])
        : "r"(a[0]), "r"(a[1]), "r"(a[2]), "r"(a[3]), "r"(b[0]), "r"(b[1]));
}
__device__ __forceinline__ float silu_f(float t) { return t / (1.f + __expf(-t)); }

// ---------------------------------------------------------------------------
// GroupNorm statistics
// ---------------------------------------------------------------------------
__global__ void zero_stats_kernel() {
    if (threadIdx.x < 16) g_stats[threadIdx.x] = 0.f;
    if (threadIdx.x >= 16 && threadIdx.x < 80) g_bias1[threadIdx.x - 16] = 0.f;
    if (threadIdx.x >= 80 && threadIdx.x < 144) g_bias2[threadIdx.x - 80] = 0.f;
}

template <int C>
__global__ void gn_reduce_kernel(const float* __restrict__ x, int n) {
    constexpr int Q = C / 4;
    constexpr int CPG = C / NGROUPS;
    int tid = blockIdx.x * blockDim.x + threadIdx.x;
    int total = gridDim.x * blockDim.x;
    int q = tid & (Q - 1);
    int g = (q * 4) / CPG;
    float s = 0.f, ss = 0.f;
    long nQ = (long)n * Q;
    const float4* xp = (const float4*)x;
    for (long e = tid; e < nQ; e += total) {
        float4 v = xp[e];
        s += (v.x + v.y) + (v.z + v.w);
        ss += v.x * v.x + v.y * v.y + v.z * v.z + v.w * v.w;
    }
    __shared__ float sh[16];
    if (threadIdx.x < 16) sh[threadIdx.x] = 0.f;
    __syncthreads();
    atomicAdd(&sh[2 * g], s);
    atomicAdd(&sh[2 * g + 1], ss);
    __syncthreads();
    if (threadIdx.x < 16) atomicAdd(&g_stats[threadIdx.x], sh[threadIdx.x]);
}

// GN stats over g_h1f16 (fp16 rows of 64 channels)
__global__ void gn_reduce_h1_kernel(int n) {
    int tid = blockIdx.x * blockDim.x + threadIdx.x;
    int total = gridDim.x * blockDim.x;
    int sub = tid & 7;                 // 8 channels per group
    float s = 0.f, ss = 0.f;
    for (long r = tid >> 3; r < n; r += (total >> 3)) {
        uint4 H = *(const uint4*)(g_h1f16 + (size_t)r * 64 + sub * 8);
        uint32_t hu[4] = {H.x, H.y, H.z, H.w};
#pragma unroll
        for (int j = 0; j < 4; ++j) {
            __half2 h2 = *reinterpret_cast<__half2*>(&hu[j]);
            float2 f = __half22float2(h2);
            s += f.x + f.y;
            ss += f.x * f.x + f.y * f.y;
        }
    }
    __shared__ float sh[16];
    if (threadIdx.x < 16) sh[threadIdx.x] = 0.f;
    __syncthreads();
    atomicAdd(&sh[2 * sub], s);
    atomicAdd(&sh[2 * sub + 1], ss);
    __syncthreads();
    if (threadIdx.x < 16) atomicAdd(&g_stats[threadIdx.x], sh[threadIdx.x]);
}

template <int C>
__global__ void gn_finalize_kernel(const float* __restrict__ gamma,
                                   const float* __restrict__ beta, int n) {
    int c = threadIdx.x;
    if (c < C) {
        int g = c / (C / NGROUPS);
        float cnt = (float)n * (C / NGROUPS);
        float mean = g_stats[2 * g] / cnt;
        float var = g_stats[2 * g + 1] / cnt - mean * mean;
        float sc = gamma[c] * rsqrtf(var + 1e-5f);
        g_scale[c] = sc;
        g_bias[c] = beta[c] - mean * sc;
    }
}

// ---------------------------------------------------------------------------
// Prep: x (fp32) -> g_xf16 (fp16)
// ---------------------------------------------------------------------------
__global__ void prep1_kernel(const float* __restrict__ x, int n) {
    int gid = blockIdx.x * blockDim.x + threadIdx.x;
    if (gid >= n * 4) return;
    int v = gid >> 2, q = gid & 3;
    const float4* src = (const float4*)(x + (size_t)v * 32 + q * 8);
    float4 a = src[0], b = src[1];
    uint32_t w[4];
    __half2 h;
    h = __floats2half2_rn(a.x, a.y); w[0] = *(uint32_t*)&h;
    h = __floats2half2_rn(a.z, a.w); w[1] = *(uint32_t*)&h;
    h = __floats2half2_rn(b.x, b.y); w[2] = *(uint32_t*)&h;
    h = __floats2half2_rn(b.z, b.w); w[3] = *(uint32_t*)&h;
    *(uint4*)(g_xf16 + (size_t)v * 32 + q * 8) = *(uint4*)w;
}

// ---------------------------------------------------------------------------
// Weight prep: fold GN scale into W, fp16, transpose to [k][n][c]
// ---------------------------------------------------------------------------
__global__ void prepW1_kernel(const float* __restrict__ W1) {
    int k = blockIdx.x, nn = threadIdx.x;
    float bs = 0.f;
    for (int c = 0; c < 32; ++c) {
        float w = W1[((size_t)(k * 32 + c)) * 64 + nn];
        bs += g_bias[c] * w;
        g_w1[((size_t)(k * 64 + nn)) * 32 + c] = __float2half_rn(w * g_scale[c]);
    }
    atomicAdd(&g_bias1[nn], bs);
}

__global__ void prepW2_kernel(const float* __restrict__ W2) {
    int k = blockIdx.x, nn = threadIdx.x;
    float bs = 0.f;
    for (int c = 0; c < 64; ++c) {
        float w = W2[((size_t)(k * 64 + c)) * 64 + nn];
        bs += g_bias[c] * w;
        g_w2[((size_t)(k * 64 + nn)) * 64 + c] = __float2half_rn(w * g_scale[c]);
    }
    atomicAdd(&g_bias2[nn], bs);
}

// ---------------------------------------------------------------------------
// mma.sync gather-conv, fp16 x fp16. One CTA = 256 voxels x 64 outputs,
// 8 warps, each warp m32 (two m16 slabs) x n64 -> every B fragment reused 2x.
// CONV2=false: CIN=32, rows 64B, 3-stage pipeline (1 sync/tap); out fp16.
// CONV2=true : CIN=64, rows 128B, 2-stage pipeline (2 syncs/tap); out fp32+=skip.
// ---------------------------------------------------------------------------
template <bool CONV2>
__global__ void __launch_bounds__(256, 2)
mma_conv_kernel(const __half* __restrict__ Araw,
                const int* __restrict__ nbr,
                const __half* __restrict__ Bw,
                const float* __restrict__ biasv,
                void* __restrict__ outp, int n) {
    constexpr uint32_t A_BYTES = CONV2 ? 32768u : 16384u;  // 256 rows
    constexpr uint32_t B_BYTES = CONV2 ? 8192u : 4096u;    // 64 rows
    constexpr uint32_t STRIDE = A_BYTES + B_BYTES;
    constexpr int NSTAGE = CONV2 ? 2 : 3;

    extern __shared__ __align__(1024) char dsmem[];
    float* sbias = (float*)dsmem;
    const uint32_t base0 = smem_to_u32(dsmem + 1024);

    const int tid = threadIdx.x;
    const int w = tid >> 5;
    const int lane = tid & 31;
    const int v0 = blockIdx.x * 256;

    if (tid < 64) sbias[tid] = biasv[tid];

    // fragment address components
    const uint32_t asel = (uint32_t)(lane >> 4);        // k-chunk low/high 8
    const int brow = lane & 7;
    const uint32_t bsel = (uint32_t)((lane >> 3) & 1);
    const int arow0 = w * 32 + (lane & 15);             // slab 0 row; slab1 = +16

    float acc[2][8][4];
#pragma unroll
    for (int s = 0; s < 2; ++s)
#pragma unroll
        for (int i = 0; i < 8; ++i)
#pragma unroll
            for (int j = 0; j < 4; ++j) acc[s][i][j] = 0.f;

    // stage loader: 1 thread per A row (256 rows)
    auto load_tap = [&](int k, uint32_t stage) {
        int vg = v0 + tid;
        if (vg >= n) vg = n - 1;
        const int idx = nbr[(long)vg * KT + k];
        if constexpr (CONV2) {
            const char* src = (const char*)Araw + (size_t)idx * 128;
            const uint32_t dr = stage + (uint32_t)tid * 128;
#pragma unroll
            for (int i = 0; i < 8; ++i)
                cp16(dr + ((((uint32_t)i ^ ((uint32_t)tid & 7)) << 4)), src + i * 16);
#pragma unroll
            for (int j = 0; j < 2; ++j) {
                int q = tid + j * 256;               // 512 chunks of 16B
                int row = q >> 3;
                uint32_t c = (uint32_t)(q & 7);
                const char* bsrc = (const char*)Bw + (size_t)k * 8192 + (size_t)q * 16;
                cp16(stage + A_BYTES + (uint32_t)row * 128 +
                         ((c ^ ((uint32_t)row & 7)) << 4),
                     bsrc);
            }
        } else {
            const char* src = (const char*)Araw + (size_t)idx * 64;
            const uint32_t dr = stage + (uint32_t)tid * 64;
#pragma unroll
            for (int i = 0; i < 4; ++i)
                cp16(dr + ((((uint32_t)i ^ ((uint32_t)tid & 3)) << 4)), src + i * 16);
            {
                int q = tid;                          // 256 chunks of 16B
                int row = q >> 2;
                uint32_t c = (uint32_t)(q & 3);
                const char* bsrc = (const char*)Bw + (size_t)k * 4096 + (size_t)q * 16;
                cp16(stage + A_BYTES + (uint32_t)row * 64 +
                         ((c ^ ((uint32_t)row & 3)) << 4),
                     bsrc);
            }
        }
    };

    // prologue
    load_tap(0, base0);
    CP_COMMIT();

    for (int k = 0; k < KT; ++k) {
        if constexpr (CONV2) {
            // 2-stage: top sync protects overwrite of stage holding tap k-1
            __syncthreads();
            if (k + 1 < KT) {
                load_tap(k + 1, base0 + (uint32_t)((k + 1) & 1) * STRIDE);
                CP_COMMIT();
                CP_WAIT(1);
            } else {
                CP_WAIT(0);
            }
            __syncthreads();
        } else {
            // 3-stage, single sync: load (k+1)%3 never collides with (k-1)%3
            if (k + 1 < KT) {
                load_tap(k + 1, base0 + (uint32_t)((k + 1) % 3) * STRIDE);
                CP_COMMIT();
                CP_WAIT(1);
            } else {
                CP_WAIT(0);
            }
            __syncthreads();
        }
        const uint32_t Ab = base0 + (uint32_t)(k % NSTAGE) * STRIDE;
        const uint32_t Bb = Ab + A_BYTES;
        if constexpr (CONV2) {
            uint32_t a[2][4][4];
#pragma unroll
            for (int s = 0; s < 2; ++s) {
                const int ar = arow0 + s * 16;
#pragma unroll
                for (int kc = 0; kc < 4; ++kc)
                    ldsm4(a[s][kc], Ab + (uint32_t)ar * 128 +
                                    ((((uint32_t)kc * 2 + asel) ^ ((uint32_t)ar & 7)) << 4));
            }
#pragma unroll
            for (int nt = 0; nt < 8; ++nt) {
#pragma unroll
                for (int kc = 0; kc < 4; ++kc) {
                    uint32_t b2[2];
                    ldsm2(b2, Bb + (uint32_t)nt * 1024 + (uint32_t)brow * 128 +
                                  ((((uint32_t)kc * 2 + bsel) ^ ((uint32_t)brow & 7)) << 4));
                    mma16816(acc[0][nt], a[0][kc], b2);
                    mma16816(acc[1][nt], a[1][kc], b2);
                }
            }
        } else {
            uint32_t a[2][2][4];
#pragma unroll
            for (int s = 0; s < 2; ++s) {
                const int ar = arow0 + s * 16;
#pragma unroll
                for (int kc = 0; kc < 2; ++kc)
                    ldsm4(a[s][kc], Ab + (uint32_t)ar * 64 +
                                    ((((uint32_t)kc * 2 + asel) ^ ((uint32_t)ar & 3)) << 4));
            }
#pragma unroll
            for (int nt = 0; nt < 8; ++nt) {
#pragma unroll
                for (int kc = 0; kc < 2; ++kc) {
                    uint32_t b2[2];
                    ldsm2(b2, Bb + (uint32_t)nt * 512 + (uint32_t)brow * 64 +
                                  ((((uint32_t)kc * 2 + bsel) ^ ((uint32_t)brow & 3)) << 4));
                    mma16816(acc[0][nt], a[0][kc], b2);
                    mma16816(acc[1][nt], a[1][kc], b2);
                }
            }
        }
        if constexpr (!CONV2) {
            // 3-stage variant needs no trailing sync (stage distance proof)
        }
    }

    // ---- epilogue ----
    const int g = lane >> 2, tg = lane & 3;
#pragma unroll
    for (int s = 0; s < 2; ++s) {
        const int row0 = v0 + w * 32 + s * 16 + g;
#pragma unroll
        for (int half = 0; half < 2; ++half) {
            int v = row0 + half * 8;
            if (v < n) {
                if constexpr (CONV2) {
                    float* po = (float*)outp + (size_t)v * 64;
#pragma unroll
                    for (int nt = 0; nt < 8; ++nt) {
                        int c = nt * 8 + tg * 2;
                        float2 sk = *(float2*)(po + c);
                        float2 rr;
                        rr.x = silu_f(acc[s][nt][half * 2 + 0] + sbias[c]) + sk.x;
                        rr.y = silu_f(acc[s][nt][half * 2 + 1] + sbias[c + 1]) + sk.y;
                        *(float2*)(po + c) = rr;
                    }
                } else {
                    char* basep = (char*)outp + (size_t)v * 128;
#pragma unroll
                    for (int nt = 0; nt < 8; ++nt) {
                        int c = nt * 8 + tg * 2;
                        float f0 = silu_f(acc[s][nt][half * 2 + 0] + sbias[c]);
                        float f1 = silu_f(acc[s][nt][half * 2 + 1] + sbias[c + 1]);
                        __half2 hh = __floats2half2_rn(f0, f1);
                        *(uint32_t*)(basep + c * 2) = *(uint32_t*)&hh;
                    }
                }
            }
        }
    }
}

// ---------------------------------------------------------------------------
// Scalar skip conv (proven): out = x @ Wskip + bskip
// ---------------------------------------------------------------------------
__global__ void __launch_bounds__(256, 2)
skip_kernel(const float* __restrict__ xin,
            const float* __restrict__ W,       // [32][64]
            const float* __restrict__ obias,   // [64]
            float* __restrict__ out, int n) {
    constexpr int TM = 256;
    __shared__ __align__(16) float As[32][TM + 4];
    __shared__ __align__(16) float Bs[32][64];

    const int tid = threadIdx.x;
    const int v0 = blockIdx.x * TM;
    const int vv = tid >> 3;
    const int ov = tid & 7;
    const int c4 = (tid & 7) << 2;

    float acc[8][8];
#pragma unroll
    for (int i = 0; i < 8; ++i)
#pragma unroll
        for (int j = 0; j < 8; ++j) acc[i][j] = 0.f;

    {
        const float4* Wp = (const float4*)W;
        float4* Bp = (float4*)(&Bs[0][0]);
        Bp[tid] = Wp[tid];
        Bp[tid + 256] = Wp[tid + 256];
#pragma unroll
        for (int it = 0; it < 8; ++it) {
            int v = it * 32 + (tid >> 3);
            int j = v0 + v;
            if (j >= n) j = n - 1;
            float4 xv = *(const float4*)(xin + (long)j * 32 + c4);
            As[c4 + 0][v] = xv.x;
            As[c4 + 1][v] = xv.y;
            As[c4 + 2][v] = xv.z;
            As[c4 + 3][v] = xv.w;
        }
        __syncthreads();
#pragma unroll
        for (int c = 0; c < 32; ++c) {
            float a[8], b[8];
            *(float4*)&a[0] = *(const float4*)&As[c][vv * 8];
            *(float4*)&a[4] = *(const float4*)&As[c][vv * 8 + 4];
            *(float4*)&b[0] = *(const float4*)&Bs[c][ov * 4];
            *(float4*)&b[4] = *(const float4*)&Bs[c][32 + ov * 4];
#pragma unroll
            for (int i = 0; i < 8; ++i)
#pragma unroll
                for (int j = 0; j < 8; ++j)
                    acc[i][j] = fmaf(a[i], b[j], acc[i][j]);
        }
    }
    float ob[8];
#pragma unroll
    for (int j = 0; j < 4; ++j) {
        ob[j] = obias[ov * 4 + j];
        ob[4 + j] = obias[32 + ov * 4 + j];
    }
#pragma unroll
    for (int i = 0; i < 8; ++i) {
        int v = v0 + vv * 8 + i;
        if (v < n) {
            float* po = out + (long)v * 64 + ov * 4;
            *(float4*)po = make_float4(acc[i][0] + ob[0], acc[i][1] + ob[1],
                                       acc[i][2] + ob[2], acc[i][3] + ob[3]);
            *(float4*)(po + 32) = make_float4(acc[i][4] + ob[4], acc[i][5] + ob[5],
                                              acc[i][6] + ob[6], acc[i][7] + ob[7]);
        }
    }
}

__global__ void fill_tail_kernel(float* out, long start, long end) {
    long i = start + (long)blockIdx.x * blockDim.x + threadIdx.x;
    if (i < end) out[i] = 0.f;
}

// ---------------------------------------------------------------------------
extern "C" void kernel_launch(void* const* d_in, const int* in_sizes, int n_in,
                              void* d_out, int out_size) {
    const float* x      = (const float*)d_in[0];
    const int*   nbr    = (const int*)d_in[1];
    const float* gamma1 = (const float*)d_in[2];
    const float* beta1  = (const float*)d_in[3];
    const float* W1     = (const float*)d_in[4];
    const float* gamma2 = (const float*)d_in[5];
    const float* beta2  = (const float*)d_in[6];
    const float* W2     = (const float*)d_in[7];
    const float* Wskip  = (const float*)d_in[8];
    const float* bskip  = (const float*)d_in[9];
    float* out = (float*)d_out;

    int n = in_sizes[0] / 32;
    int nblk = (n + 255) / 256;
    int nblk_mma = (n + 255) / 256;

    __half *xf16p = nullptr, *h1p = nullptr, *w1p = nullptr, *w2p = nullptr;
    float *b1p = nullptr, *b2p = nullptr;
    cudaGetSymbolAddress((void**)&xf16p, g_xf16);
    cudaGetSymbolAddress((void**)&h1p, g_h1f16);
    cudaGetSymbolAddress((void**)&w1p, g_w1);
    cudaGetSymbolAddress((void**)&w2p, g_w2);
    cudaGetSymbolAddress((void**)&b1p, g_bias1);
    cudaGetSymbolAddress((void**)&b2p, g_bias2);

    const int SMEM1 = 1024 + 3 * (16384 + 4096);    // 62464
    const int SMEM2 = 1024 + 2 * (32768 + 8192);    // 82944
    cudaFuncSetAttribute(mma_conv_kernel<false>,
                         cudaFuncAttributeMaxDynamicSharedMemorySize, SMEM1);
    cudaFuncSetAttribute(mma_conv_kernel<true>,
                         cudaFuncAttributeMaxDynamicSharedMemorySize, SMEM2);

    // skip path first (conv2 epilogue accumulates onto it)
    skip_kernel<<<nblk, 256>>>(x, Wskip, bskip, out, n);

    // GN1 stats + prep
    zero_stats_kernel<<<1, 160>>>();
    gn_reduce_kernel<32><<<1184, 256>>>(x, n);
    gn_finalize_kernel<32><<<1, 64>>>(gamma1, beta1, n);
    prep1_kernel<<<(n * 4 + 255) / 256, 256>>>(x, n);
    prepW1_kernel<<<KT, 64>>>(W1);

    // conv1 -> g_h1f16 (fp16, post-SiLU)
    mma_conv_kernel<false><<<nblk_mma, 256, SMEM1>>>(
        xf16p, nbr, w1p, b1p, (void*)h1p, n);

    // GN2 stats from fp16 h1
    zero_stats_kernel<<<1, 16>>>();
    gn_reduce_h1_kernel<<<1184, 256>>>(n);
    gn_finalize_kernel<64><<<1, 64>>>(gamma2, beta2, n);
    prepW2_kernel<<<KT, 64>>>(W2);

    // conv2 -> out (accumulates skip)
    mma_conv_kernel<true><<<nblk_mma, 256, SMEM2>>>(
        h1p, nbr, w2p, b2p, (void*)out, n);

    long main_elems = (long)n * 64;
    if ((long)out_size > main_elems) {
        long tail = (long)out_size - main_elems;
        int tb = (int)((tail + 255) / 256);
        fill_tail_kernel<<<tb, 256>>>(out, main_elems, (long)out_size);
    }
}

// round 8
// speedup vs baseline: 4.6936x; 1.1406x over previous
#include <cuda_runtime.h>
#include <cuda_fp16.h>
#include <math.h>
#include <stdint.h>

#define NMAX 500000
#define NGROUPS 8
#define KT 27

// ---------------------------------------------------------------------------
// Device global scratch (no allocation allowed in kernel_launch)
// ---------------------------------------------------------------------------
__device__ __half g_xf16[(size_t)NMAX * 32];    // activations conv1, fp16 rows 64B
__device__ __half g_h1f16[(size_t)NMAX * 64];   // conv1 output (post-SiLU), rows 128B
__device__ __half g_w1[KT * 64 * 32];           // [k][n][c]
__device__ __half g_w2[KT * 64 * 64];           // [k][n][c]
__device__ int g_nbrt[(size_t)KT * NMAX];       // transposed neighbor idx [k][v]
__device__ float g_bias1[64];
__device__ float g_bias2[64];
__device__ float g_stats[16];
__device__ float g_scale[64];
__device__ float g_bias[64];

// ---------------------------------------------------------------------------
// Helpers
// ---------------------------------------------------------------------------
__device__ __forceinline__ uint32_t smem_to_u32(const void* p) {
    uint32_t a;
    asm("{ .reg .u64 t; cvta.to.shared.u64 t, %1; cvt.u32.u64 %0, t; }" : "=r"(a) : "l"(p));
    return a;
}
__device__ __forceinline__ void cp16(uint32_t dst, const void* src) {
    asm volatile("cp.async.cg.shared.global [%0], [%1], 16;" :: "r"(dst), "l"(src));
}
#define CP_COMMIT() asm volatile("cp.async.commit_group;" ::: "memory")
#define CP_WAIT(N) asm volatile("cp.async.wait_group %0;" :: "n"(N) : "memory")

__device__ __forceinline__ void ldsm4(uint32_t* r, uint32_t addr) {
    asm volatile("ldmatrix.sync.aligned.m8n8.x4.shared.b16 {%0,%1,%2,%3}, [%4];"
                 : "=r"(r[0]), "=r"(r[1]), "=r"(r[2]), "=r"(r[3]) : "r"(addr));
}
__device__ __forceinline__ void ldsm2(uint32_t* r, uint32_t addr) {
    asm volatile("ldmatrix.sync.aligned.m8n8.x2.shared.b16 {%0,%1}, [%2];"
                 : "=r"(r[0]), "=r"(r[1]) : "r"(addr));
}
__device__ __forceinline__ void mma16816(float* d, const uint32_t* a, const uint32_t* b) {
    asm volatile(
        "mma.sync.aligned.m16n8k16.row.col.f32.f16.f16.f32 "
        "{%0,%1,%2,%3}, {%4,%5,%6,%7}, {%8,%9}, {%0,%1,%2,%3};"
        : "+f"(d[0]), "+f"(d[1]), "+f"(d[2]), "+f"(d[3])
        : "r"(a[0]), "r"(a[1]), "r"(a[2]), "r"(a[3]), "r"(b[0]), "r"(b[1]));
}
__device__ __forceinline__ float silu_f(float t) { return t / (1.f + __expf(-t)); }

// ---------------------------------------------------------------------------
// GroupNorm statistics
// ---------------------------------------------------------------------------
__global__ void zero_stats_kernel() {
    if (threadIdx.x < 16) g_stats[threadIdx.x] = 0.f;
    if (threadIdx.x >= 16 && threadIdx.x < 80) g_bias1[threadIdx.x - 16] = 0.f;
    if (threadIdx.x >= 80 && threadIdx.x < 144) g_bias2[threadIdx.x - 80] = 0.f;
}

template <int C>
__global__ void gn_reduce_kernel(const float* __restrict__ x, int n) {
    constexpr int Q = C / 4;
    constexpr int CPG = C / NGROUPS;
    int tid = blockIdx.x * blockDim.x + threadIdx.x;
    int total = gridDim.x * blockDim.x;
    int q = tid & (Q - 1);
    int g = (q * 4) / CPG;
    float s = 0.f, ss = 0.f;
    long nQ = (long)n * Q;
    const float4* xp = (const float4*)x;
    for (long e = tid; e < nQ; e += total) {
        float4 v = xp[e];
        s += (v.x + v.y) + (v.z + v.w);
        ss += v.x * v.x + v.y * v.y + v.z * v.z + v.w * v.w;
    }
    __shared__ float sh[16];
    if (threadIdx.x < 16) sh[threadIdx.x] = 0.f;
    __syncthreads();
    atomicAdd(&sh[2 * g], s);
    atomicAdd(&sh[2 * g + 1], ss);
    __syncthreads();
    if (threadIdx.x < 16) atomicAdd(&g_stats[threadIdx.x], sh[threadIdx.x]);
}

// GN stats over g_h1f16 (fp16 rows of 64 channels)
__global__ void gn_reduce_h1_kernel(int n) {
    int tid = blockIdx.x * blockDim.x + threadIdx.x;
    int total = gridDim.x * blockDim.x;
    int sub = tid & 7;                 // 8 channels per group
    float s = 0.f, ss = 0.f;
    for (long r = tid >> 3; r < n; r += (total >> 3)) {
        uint4 H = *(const uint4*)(g_h1f16 + (size_t)r * 64 + sub * 8);
        uint32_t hu[4] = {H.x, H.y, H.z, H.w};
#pragma unroll
        for (int j = 0; j < 4; ++j) {
            __half2 h2 = *reinterpret_cast<__half2*>(&hu[j]);
            float2 f = __half22float2(h2);
            s += f.x + f.y;
            ss += f.x * f.x + f.y * f.y;
        }
    }
    __shared__ float sh[16];
    if (threadIdx.x < 16) sh[threadIdx.x] = 0.f;
    __syncthreads();
    atomicAdd(&sh[2 * sub], s);
    atomicAdd(&sh[2 * sub + 1], ss);
    __syncthreads();
    if (threadIdx.x < 16) atomicAdd(&g_stats[threadIdx.x], sh[threadIdx.x]);
}

template <int C>
__global__ void gn_finalize_kernel(const float* __restrict__ gamma,
                                   const float* __restrict__ beta, int n) {
    int c = threadIdx.x;
    if (c < C) {
        int g = c / (C / NGROUPS);
        float cnt = (float)n * (C / NGROUPS);
        float mean = g_stats[2 * g] / cnt;
        float var = g_stats[2 * g + 1] / cnt - mean * mean;
        float sc = gamma[c] * rsqrtf(var + 1e-5f);
        g_scale[c] = sc;
        g_bias[c] = beta[c] - mean * sc;
    }
}

// ---------------------------------------------------------------------------
// Prep: x (fp32) -> g_xf16 (fp16)
// ---------------------------------------------------------------------------
__global__ void prep1_kernel(const float* __restrict__ x, int n) {
    int gid = blockIdx.x * blockDim.x + threadIdx.x;
    if (gid >= n * 4) return;
    int v = gid >> 2, q = gid & 3;
    const float4* src = (const float4*)(x + (size_t)v * 32 + q * 8);
    float4 a = src[0], b = src[1];
    uint32_t w[4];
    __half2 h;
    h = __floats2half2_rn(a.x, a.y); w[0] = *(uint32_t*)&h;
    h = __floats2half2_rn(a.z, a.w); w[1] = *(uint32_t*)&h;
    h = __floats2half2_rn(b.x, b.y); w[2] = *(uint32_t*)&h;
    h = __floats2half2_rn(b.z, b.w); w[3] = *(uint32_t*)&h;
    *(uint4*)(g_xf16 + (size_t)v * 32 + q * 8) = *(uint4*)w;
}

// ---------------------------------------------------------------------------
// Prep: transpose nbr [v][k] -> g_nbrt [k][v] (coalesced per-tap reads later)
// ---------------------------------------------------------------------------
__global__ void prep_nbr_kernel(const int* __restrict__ nbr, int n) {
    int v = blockIdx.x * blockDim.x + threadIdx.x;
    if (v >= n) return;
#pragma unroll
    for (int k = 0; k < KT; ++k)
        g_nbrt[(size_t)k * n + v] = nbr[(size_t)v * KT + k];
}

// ---------------------------------------------------------------------------
// Weight prep: fold GN scale into W, fp16, transpose to [k][n][c]
// ---------------------------------------------------------------------------
__global__ void prepW1_kernel(const float* __restrict__ W1) {
    int k = blockIdx.x, nn = threadIdx.x;
    float bs = 0.f;
    for (int c = 0; c < 32; ++c) {
        float w = W1[((size_t)(k * 32 + c)) * 64 + nn];
        bs += g_bias[c] * w;
        g_w1[((size_t)(k * 64 + nn)) * 32 + c] = __float2half_rn(w * g_scale[c]);
    }
    atomicAdd(&g_bias1[nn], bs);
}

__global__ void prepW2_kernel(const float* __restrict__ W2) {
    int k = blockIdx.x, nn = threadIdx.x;
    float bs = 0.f;
    for (int c = 0; c < 64; ++c) {
        float w = W2[((size_t)(k * 64 + c)) * 64 + nn];
        bs += g_bias[c] * w;
        g_w2[((size_t)(k * 64 + nn)) * 64 + c] = __float2half_rn(w * g_scale[c]);
    }
    atomicAdd(&g_bias2[nn], bs);
}

// ---------------------------------------------------------------------------
// mma.sync gather-conv, fp16 x fp16. One CTA = 256 voxels x 64 outputs,
// 8 warps, each warp m32 (two m16 slabs) x n64 (B fragments reused 2x).
// Gather uses lane-per-chunk mapping: consecutive lanes cover one full row,
// so each cp.async instruction touches few 128B lines (L1tex wavefronts ~min).
// CONV2=false: CIN=32, rows 64B, 3-stage pipeline; out fp16.
// CONV2=true : CIN=64, rows 128B, 2-stage pipeline; out fp32 += skip.
// ---------------------------------------------------------------------------
template <bool CONV2>
__global__ void __launch_bounds__(256, 2)
mma_conv_kernel(const __half* __restrict__ Araw,
                const int* __restrict__ nbrt,   // [k][v]
                const __half* __restrict__ Bw,
                const float* __restrict__ biasv,
                void* __restrict__ outp, int n) {
    constexpr uint32_t A_BYTES = CONV2 ? 32768u : 16384u;  // 256 rows
    constexpr uint32_t B_BYTES = CONV2 ? 8192u : 4096u;    // 64 rows
    constexpr uint32_t STRIDE = A_BYTES + B_BYTES;
    constexpr int NSTAGE = CONV2 ? 2 : 3;

    extern __shared__ __align__(1024) char dsmem[];
    float* sbias = (float*)dsmem;
    const uint32_t base0 = smem_to_u32(dsmem + 1024);

    const int tid = threadIdx.x;
    const int w = tid >> 5;
    const int lane = tid & 31;
    const int v0 = blockIdx.x * 256;

    if (tid < 64) sbias[tid] = biasv[tid];

    // fragment address components
    const uint32_t asel = (uint32_t)(lane >> 4);        // k-chunk low/high 8
    const int brow = lane & 7;
    const uint32_t bsel = (uint32_t)((lane >> 3) & 1);
    const int arow0 = w * 32 + (lane & 15);             // slab 0 row; slab1 = +16

    float acc[2][8][4];
#pragma unroll
    for (int s = 0; s < 2; ++s)
#pragma unroll
        for (int i = 0; i < 8; ++i)
#pragma unroll
            for (int j = 0; j < 4; ++j) acc[s][i][j] = 0.f;

    // stage loader: consecutive lanes cover one row's 16B chunks
    auto load_tap = [&](int k, uint32_t stage) {
        const int* nt = nbrt + (size_t)k * n;
        if constexpr (CONV2) {
            const int lrow = tid >> 3, lchk = tid & 7;   // 32 rows/pass, 8 passes
#pragma unroll
            for (int p = 0; p < 8; ++p) {
                int row = p * 32 + lrow;
                int vg = v0 + row;
                if (vg >= n) vg = n - 1;
                int idx = __ldg(&nt[vg]);
                cp16(stage + (uint32_t)row * 128 +
                         (((uint32_t)lchk ^ ((uint32_t)row & 7)) << 4),
                     (const char*)Araw + (size_t)idx * 128 + lchk * 16);
            }
#pragma unroll
            for (int j = 0; j < 2; ++j) {
                int q = tid + j * 256;               // 512 chunks of 16B
                int row = q >> 3;
                uint32_t c = (uint32_t)(q & 7);
                cp16(stage + A_BYTES + (uint32_t)row * 128 +
                         ((c ^ ((uint32_t)row & 7)) << 4),
                     (const char*)Bw + (size_t)k * 8192 + (size_t)q * 16);
            }
        } else {
            const int lrow = tid >> 2, lchk = tid & 3;   // 64 rows/pass, 4 passes
#pragma unroll
            for (int p = 0; p < 4; ++p) {
                int row = p * 64 + lrow;
                int vg = v0 + row;
                if (vg >= n) vg = n - 1;
                int idx = __ldg(&nt[vg]);
                cp16(stage + (uint32_t)row * 64 +
                         (((uint32_t)lchk ^ ((uint32_t)row & 3)) << 4),
                     (const char*)Araw + (size_t)idx * 64 + lchk * 16);
            }
            {
                int q = tid;                          // 256 chunks of 16B
                int row = q >> 2;
                uint32_t c = (uint32_t)(q & 3);
                cp16(stage + A_BYTES + (uint32_t)row * 64 +
                         ((c ^ ((uint32_t)row & 3)) << 4),
                     (const char*)Bw + (size_t)k * 4096 + (size_t)q * 16);
            }
        }
    };

    // prologue
    load_tap(0, base0);
    CP_COMMIT();

    for (int k = 0; k < KT; ++k) {
        if constexpr (CONV2) {
            // 2-stage: top sync protects overwrite of stage holding tap k-1
            __syncthreads();
            if (k + 1 < KT) {
                load_tap(k + 1, base0 + (uint32_t)((k + 1) & 1) * STRIDE);
                CP_COMMIT();
                CP_WAIT(1);
            } else {
                CP_WAIT(0);
            }
            __syncthreads();
        } else {
            // 3-stage, single sync: load (k+1)%3 never collides with (k-1)%3
            if (k + 1 < KT) {
                load_tap(k + 1, base0 + (uint32_t)((k + 1) % 3) * STRIDE);
                CP_COMMIT();
                CP_WAIT(1);
            } else {
                CP_WAIT(0);
            }
            __syncthreads();
        }
        const uint32_t Ab = base0 + (uint32_t)(k % NSTAGE) * STRIDE;
        const uint32_t Bb = Ab + A_BYTES;
        if constexpr (CONV2) {
            uint32_t a[2][4][4];
#pragma unroll
            for (int s = 0; s < 2; ++s) {
                const int ar = arow0 + s * 16;
#pragma unroll
                for (int kc = 0; kc < 4; ++kc)
                    ldsm4(a[s][kc], Ab + (uint32_t)ar * 128 +
                                    ((((uint32_t)kc * 2 + asel) ^ ((uint32_t)ar & 7)) << 4));
            }
#pragma unroll
            for (int nt = 0; nt < 8; ++nt) {
#pragma unroll
                for (int kc = 0; kc < 4; ++kc) {
                    uint32_t b2[2];
                    ldsm2(b2, Bb + (uint32_t)nt * 1024 + (uint32_t)brow * 128 +
                                  ((((uint32_t)kc * 2 + bsel) ^ ((uint32_t)brow & 7)) << 4));
                    mma16816(acc[0][nt], a[0][kc], b2);
                    mma16816(acc[1][nt], a[1][kc], b2);
                }
            }
        } else {
            uint32_t a[2][2][4];
#pragma unroll
            for (int s = 0; s < 2; ++s) {
                const int ar = arow0 + s * 16;
#pragma unroll
                for (int kc = 0; kc < 2; ++kc)
                    ldsm4(a[s][kc], Ab + (uint32_t)ar * 64 +
                                    ((((uint32_t)kc * 2 + asel) ^ ((uint32_t)ar & 3)) << 4));
            }
#pragma unroll
            for (int nt = 0; nt < 8; ++nt) {
#pragma unroll
                for (int kc = 0; kc < 2; ++kc) {
                    uint32_t b2[2];
                    ldsm2(b2, Bb + (uint32_t)nt * 512 + (uint32_t)brow * 64 +
                                  ((((uint32_t)kc * 2 + bsel) ^ ((uint32_t)brow & 3)) << 4));
                    mma16816(acc[0][nt], a[0][kc], b2);
                    mma16816(acc[1][nt], a[1][kc], b2);
                }
            }
        }
    }

    // ---- epilogue ----
    const int g = lane >> 2, tg = lane & 3;
#pragma unroll
    for (int s = 0; s < 2; ++s) {
        const int row0 = v0 + w * 32 + s * 16 + g;
#pragma unroll
        for (int half = 0; half < 2; ++half) {
            int v = row0 + half * 8;
            if (v < n) {
                if constexpr (CONV2) {
                    float* po = (float*)outp + (size_t)v * 64;
#pragma unroll
                    for (int nt = 0; nt < 8; ++nt) {
                        int c = nt * 8 + tg * 2;
                        float2 sk = *(float2*)(po + c);
                        float2 rr;
                        rr.x = silu_f(acc[s][nt][half * 2 + 0] + sbias[c]) + sk.x;
                        rr.y = silu_f(acc[s][nt][half * 2 + 1] + sbias[c + 1]) + sk.y;
                        *(float2*)(po + c) = rr;
                    }
                } else {
                    char* basep = (char*)outp + (size_t)v * 128;
#pragma unroll
                    for (int nt = 0; nt < 8; ++nt) {
                        int c = nt * 8 + tg * 2;
                        float f0 = silu_f(acc[s][nt][half * 2 + 0] + sbias[c]);
                        float f1 = silu_f(acc[s][nt][half * 2 + 1] + sbias[c + 1]);
                        __half2 hh = __floats2half2_rn(f0, f1);
                        *(uint32_t*)(basep + c * 2) = *(uint32_t*)&hh;
                    }
                }
            }
        }
    }
}

// ---------------------------------------------------------------------------
// Scalar skip conv (proven): out = x @ Wskip + bskip
// ---------------------------------------------------------------------------
__global__ void __launch_bounds__(256, 2)
skip_kernel(const float* __restrict__ xin,
            const float* __restrict__ W,       // [32][64]
            const float* __restrict__ obias,   // [64]
            float* __restrict__ out, int n) {
    constexpr int TM = 256;
    __shared__ __align__(16) float As[32][TM + 4];
    __shared__ __align__(16) float Bs[32][64];

    const int tid = threadIdx.x;
    const int v0 = blockIdx.x * TM;
    const int vv = tid >> 3;
    const int ov = tid & 7;
    const int c4 = (tid & 7) << 2;

    float acc[8][8];
#pragma unroll
    for (int i = 0; i < 8; ++i)
#pragma unroll
        for (int j = 0; j < 8; ++j) acc[i][j] = 0.f;

    {
        const float4* Wp = (const float4*)W;
        float4* Bp = (float4*)(&Bs[0][0]);
        Bp[tid] = Wp[tid];
        Bp[tid + 256] = Wp[tid + 256];
#pragma unroll
        for (int it = 0; it < 8; ++it) {
            int v = it * 32 + (tid >> 3);
            int j = v0 + v;
            if (j >= n) j = n - 1;
            float4 xv = *(const float4*)(xin + (long)j * 32 + c4);
            As[c4 + 0][v] = xv.x;
            As[c4 + 1][v] = xv.y;
            As[c4 + 2][v] = xv.z;
            As[c4 + 3][v] = xv.w;
        }
        __syncthreads();
#pragma unroll
        for (int c = 0; c < 32; ++c) {
            float a[8], b[8];
            *(float4*)&a[0] = *(const float4*)&As[c][vv * 8];
            *(float4*)&a[4] = *(const float4*)&As[c][vv * 8 + 4];
            *(float4*)&b[0] = *(const float4*)&Bs[c][ov * 4];
            *(float4*)&b[4] = *(const float4*)&Bs[c][32 + ov * 4];
#pragma unroll
            for (int i = 0; i < 8; ++i)
#pragma unroll
                for (int j = 0; j < 8; ++j)
                    acc[i][j] = fmaf(a[i], b[j], acc[i][j]);
        }
    }
    float ob[8];
#pragma unroll
    for (int j = 0; j < 4; ++j) {
        ob[j] = obias[ov * 4 + j];
        ob[4 + j] = obias[32 + ov * 4 + j];
    }
#pragma unroll
    for (int i = 0; i < 8; ++i) {
        int v = v0 + vv * 8 + i;
        if (v < n) {
            float* po = out + (long)v * 64 + ov * 4;
            *(float4*)po = make_float4(acc[i][0] + ob[0], acc[i][1] + ob[1],
                                       acc[i][2] + ob[2], acc[i][3] + ob[3]);
            *(float4*)(po + 32) = make_float4(acc[i][4] + ob[4], acc[i][5] + ob[5],
                                              acc[i][6] + ob[6], acc[i][7] + ob[7]);
        }
    }
}

__global__ void fill_tail_kernel(float* out, long start, long end) {
    long i = start + (long)blockIdx.x * blockDim.x + threadIdx.x;
    if (i < end) out[i] = 0.f;
}

// ---------------------------------------------------------------------------
extern "C" void kernel_launch(void* const* d_in, const int* in_sizes, int n_in,
                              void* d_out, int out_size) {
    const float* x      = (const float*)d_in[0];
    const int*   nbr    = (const int*)d_in[1];
    const float* gamma1 = (const float*)d_in[2];
    const float* beta1  = (const float*)d_in[3];
    const float* W1     = (const float*)d_in[4];
    const float* gamma2 = (const float*)d_in[5];
    const float* beta2  = (const float*)d_in[6];
    const float* W2     = (const float*)d_in[7];
    const float* Wskip  = (const float*)d_in[8];
    const float* bskip  = (const float*)d_in[9];
    float* out = (float*)d_out;

    int n = in_sizes[0] / 32;
    int nblk = (n + 255) / 256;
    int nblk_mma = (n + 255) / 256;

    __half *xf16p = nullptr, *h1p = nullptr, *w1p = nullptr, *w2p = nullptr;
    float *b1p = nullptr, *b2p = nullptr;
    int *nbrtp = nullptr;
    cudaGetSymbolAddress((void**)&xf16p, g_xf16);
    cudaGetSymbolAddress((void**)&h1p, g_h1f16);
    cudaGetSymbolAddress((void**)&w1p, g_w1);
    cudaGetSymbolAddress((void**)&w2p, g_w2);
    cudaGetSymbolAddress((void**)&b1p, g_bias1);
    cudaGetSymbolAddress((void**)&b2p, g_bias2);
    cudaGetSymbolAddress((void**)&nbrtp, g_nbrt);

    const int SMEM1 = 1024 + 3 * (16384 + 4096);    // 62464
    const int SMEM2 = 1024 + 2 * (32768 + 8192);    // 82944
    cudaFuncSetAttribute(mma_conv_kernel<false>,
                         cudaFuncAttributeMaxDynamicSharedMemorySize, SMEM1);
    cudaFuncSetAttribute(mma_conv_kernel<true>,
                         cudaFuncAttributeMaxDynamicSharedMemorySize, SMEM2);

    // skip path first (conv2 epilogue accumulates onto it)
    skip_kernel<<<nblk, 256>>>(x, Wskip, bskip, out, n);

    // nbr transpose + GN1 stats + prep
    prep_nbr_kernel<<<nblk, 256>>>(nbr, n);
    zero_stats_kernel<<<1, 160>>>();
    gn_reduce_kernel<32><<<1184, 256>>>(x, n);
    gn_finalize_kernel<32><<<1, 64>>>(gamma1, beta1, n);
    prep1_kernel<<<(n * 4 + 255) / 256, 256>>>(x, n);
    prepW1_kernel<<<KT, 64>>>(W1);

    // conv1 -> g_h1f16 (fp16, post-SiLU)
    mma_conv_kernel<false><<<nblk_mma, 256, SMEM1>>>(
        xf16p, nbrtp, w1p, b1p, (void*)h1p, n);

    // GN2 stats from fp16 h1
    zero_stats_kernel<<<1, 16>>>();
    gn_reduce_h1_kernel<<<1184, 256>>>(n);
    gn_finalize_kernel<64><<<1, 64>>>(gamma2, beta2, n);
    prepW2_kernel<<<KT, 64>>>(W2);

    // conv2 -> out (accumulates skip)
    mma_conv_kernel<true><<<nblk_mma, 256, SMEM2>>>(
        h1p, nbrtp, w2p, b2p, (void*)out, n);

    long main_elems = (long)n * 64;
    if ((long)out_size > main_elems) {
        long tail = (long)out_size - main_elems;
        int tb = (int)((tail + 255) / 256);
        fill_tail_kernel<<<tb, 256>>>(out, main_elems, (long)out_size);
    }
}